// round 12
// baseline (speedup 1.0000x reference)
#include <cuda_runtime.h>
#include <cuda_bf16.h>
#include <cstdint>
#include <stdint.h>
#include <float.h>
#include <math.h>

#define MAX_NODES 100000
#define MAX_EDGES 600000
#define MAX_GRAPHS 512

// ---------------- scratch (device globals) ----------------
__device__ float g_h1[(size_t)MAX_NODES * 128];
__device__ float g_o1[(size_t)MAX_NODES * 128];
__device__ float g_h2[(size_t)MAX_NODES * 64];
__device__ float g_o2[(size_t)MAX_NODES * 64];
__device__ float g_as1[MAX_NODES * 2];
__device__ float g_ad1[MAX_NODES * 2];
__device__ float g_as2[MAX_NODES];
__device__ float g_ad2[MAX_NODES];
// fragment-packed weights: word idx = ((n*8+ks)*4+j)*4 + {hi_k, hi_k8, lo_k, lo_k8}
__device__ uint32_t g_w1pk[128 * 128];
__device__ uint32_t g_w2pk[64 * 128];
__device__ int g_deg[MAX_NODES];
__device__ int g_incl[MAX_NODES];
__device__ int g_bsum[256];
__device__ int g_rowptr[MAX_NODES + 1];
__device__ int g_cursor[MAX_NODES];
__device__ int g_adj[MAX_EDGES + MAX_NODES];
__device__ float g_psum[MAX_GRAPHS * 64];
__device__ float g_pmax[MAX_GRAPHS * 64];
__device__ float g_cnt[MAX_GRAPHS];

// ---------------- misc ----------------
__device__ __forceinline__ void atomicMaxF(float* addr, float value) {
    if (value >= 0.f) {
        atomicMax((int*)addr, __float_as_int(value));
    } else {
        atomicMin((unsigned int*)addr, __float_as_uint(value));
    }
}

__device__ __forceinline__ void mma_bf16(float* d, const uint32_t* a, uint32_t b0, uint32_t b1) {
    asm volatile(
        "mma.sync.aligned.m16n8k16.row.col.f32.bf16.bf16.f32 "
        "{%0, %1, %2, %3}, {%4, %5, %6, %7}, {%8, %9}, {%0, %1, %2, %3};"
        : "+f"(d[0]), "+f"(d[1]), "+f"(d[2]), "+f"(d[3])
        : "r"(a[0]), "r"(a[1]), "r"(a[2]), "r"(a[3]), "r"(b0), "r"(b1));
}

__device__ __forceinline__ void cvt_hilo(float2 x, uint32_t& hi, uint32_t& lo) {
    __nv_bfloat16 h0 = __float2bfloat16(x.x);
    __nv_bfloat16 h1 = __float2bfloat16(x.y);
    __nv_bfloat16 l0 = __float2bfloat16(x.x - __bfloat162float(h0));
    __nv_bfloat16 l1 = __float2bfloat16(x.y - __bfloat162float(h1));
    hi = (uint32_t)__bfloat16_as_ushort(h0) | ((uint32_t)__bfloat16_as_ushort(h1) << 16);
    lo = (uint32_t)__bfloat16_as_ushort(l0) | ((uint32_t)__bfloat16_as_ushort(l1) << 16);
}

// ---------------- setup: deg=1 + fragment-packed weight preps + pool fills ----------------
__global__ void setup_kernel(const float* __restrict__ W1, const float* __restrict__ W2,
                             uint32_t* __restrict__ w1pk, uint32_t* __restrict__ w2pk,
                             int* __restrict__ deg, float* __restrict__ psum,
                             float* __restrict__ pmax, float* __restrict__ cnt, int n, int gtot) {
    int idx = blockIdx.x * blockDim.x + threadIdx.x;
    if (idx < n) deg[idx] = 1;
    if (idx < 128 * 64) {
        int nr = idx >> 6;
        int p = idx & 63;
        int k0 = p * 2;
        int ks = k0 >> 4;
        int r = k0 & 15;
        int halfk = r >> 3;
        int j = (r & 7) >> 1;
        float2 v = make_float2(W1[k0 * 128 + nr], W1[(k0 + 1) * 128 + nr]);
        uint32_t hw;
        uint32_t lw;
        cvt_hilo(v, hw, lw);
        int base = ((nr * 8 + ks) * 4 + j) * 4;
        w1pk[base + halfk] = hw;
        w1pk[base + 2 + halfk] = lw;
    }
    if (idx < 64 * 64) {
        int nr = idx >> 6;
        int p = idx & 63;
        int k0 = p * 2;
        int ks = k0 >> 4;
        int r = k0 & 15;
        int halfk = r >> 3;
        int j = (r & 7) >> 1;
        float2 v = make_float2(W2[k0 * 64 + nr], W2[(k0 + 1) * 64 + nr]);
        uint32_t hw;
        uint32_t lw;
        cvt_hilo(v, hw, lw);
        int base = ((nr * 8 + ks) * 4 + j) * 4;
        w2pk[base + halfk] = hw;
        w2pk[base + 2 + halfk] = lw;
    }
    if (idx < gtot * 64) {
        psum[idx] = 0.f;
        pmax[idx] = -FLT_MAX;
    }
    if (idx < gtot) cnt[idx] = 0.f;
}

// ---------------- HMMA GEMM, one head per CTA ----------------
// grid = (cdiv(n,128), HEADS); CTA computes 128 rows x 64 cols.
// warp = 16 rows x 8 n-tiles; acc = 32 regs -> 3 CTAs/SM.
template <int HEADS>
__global__ __launch_bounds__(256, 3) void gemm_head(
    const float* __restrict__ A, const uint32_t* __restrict__ Wpk,
    const float* __restrict__ avs, const float* __restrict__ avd, float* __restrict__ Hout,
    float* __restrict__ as_out, float* __restrict__ ad_out, int n) {
    extern __shared__ __align__(16) char sm[];
    constexpr int NOUT = HEADS * 64;  // Hout row stride
    constexpr int NT = 8;
    constexpr int WST = 576;
    const uint32_t OFF_AVS = 0;
    const uint32_t OFF_AVD = 256;
    const uint32_t OFF_W = 512;

    const int tid = threadIdx.x;
    const int row0 = blockIdx.x * 128;
    const int head = blockIdx.y;
    const uint32_t* Wh = Wpk + head * 64 * 128;

    if (tid < 64) {
        reinterpret_cast<float*>(sm + OFF_AVS)[tid] = avs[head * 64 + tid];
        reinterpret_cast<float*>(sm + OFF_AVD)[tid] = avd[head * 64 + tid];
    }
    {
        const uint4* wsrc = reinterpret_cast<const uint4*>(Wh);
#pragma unroll
        for (int i = tid; i < 64 * 32; i += 256) {
            int nr = i >> 5;
            int w = i & 31;
            *reinterpret_cast<uint4*>(sm + OFF_W + nr * WST + w * 16) = wsrc[i];
        }
    }
    __syncthreads();

    const int warp = tid >> 5;
    const int lane = tid & 31;
    const int g = lane >> 2;
    const int j = lane & 3;
    const int wm0 = warp * 16;

    const int rowA0 = row0 + wm0 + g;
    const int rowA1 = rowA0 + 8;
    const bool v0r = rowA0 < n;
    const bool v1r = rowA1 < n;
    const float* a0p = A + (size_t)rowA0 * 128 + j * 2;
    const float* a1p = A + (size_t)rowA1 * 128 + j * 2;

    float acc[NT][4];
#pragma unroll
    for (int nt = 0; nt < NT; nt++)
#pragma unroll
        for (int q = 0; q < 4; q++) acc[nt][q] = 0.f;

    const char* bw = sm + OFF_W + g * WST + j * 16;
    const float2 z2 = make_float2(0.f, 0.f);
#pragma unroll
    for (int ks = 0; ks < 8; ks++) {
        float2 x00 = v0r ? *reinterpret_cast<const float2*>(a0p + ks * 16) : z2;
        float2 x01 = v0r ? *reinterpret_cast<const float2*>(a0p + ks * 16 + 8) : z2;
        float2 x10 = v1r ? *reinterpret_cast<const float2*>(a1p + ks * 16) : z2;
        float2 x11 = v1r ? *reinterpret_cast<const float2*>(a1p + ks * 16 + 8) : z2;
        uint32_t ahi[4];
        uint32_t alo[4];
        cvt_hilo(x00, ahi[0], alo[0]);
        cvt_hilo(x10, ahi[1], alo[1]);
        cvt_hilo(x01, ahi[2], alo[2]);
        cvt_hilo(x11, ahi[3], alo[3]);
        const char* bks = bw + ks * 64;
#pragma unroll
        for (int nt = 0; nt < NT; nt++) {
            uint4 b = *reinterpret_cast<const uint4*>(bks + nt * 8 * WST);
            mma_bf16(acc[nt], ahi, b.x, b.y);
            mma_bf16(acc[nt], ahi, b.z, b.w);
            mma_bf16(acc[nt], alo, b.x, b.y);
        }
    }

    // epilogue: alpha partials for this head + direct C stores
    const float* avs_s = reinterpret_cast<const float*>(sm + OFF_AVS);
    const float* avd_s = reinterpret_cast<const float*>(sm + OFF_AVD);
    float asum[2] = {0.f, 0.f};
    float dsum[2] = {0.f, 0.f};
#pragma unroll
    for (int nt = 0; nt < NT; nt++) {
        int cn = nt * 8 + 2 * j;
        float av0 = avs_s[cn];
        float av1 = avs_s[cn + 1];
        float dv0 = avd_s[cn];
        float dv1 = avd_s[cn + 1];
        asum[0] += acc[nt][0] * av0 + acc[nt][1] * av1;
        asum[1] += acc[nt][2] * av0 + acc[nt][3] * av1;
        dsum[0] += acc[nt][0] * dv0 + acc[nt][1] * dv1;
        dsum[1] += acc[nt][2] * dv0 + acc[nt][3] * dv1;
        int col = head * 64 + cn;
        if (v0r)
            *reinterpret_cast<float2*>(Hout + (size_t)rowA0 * NOUT + col) =
                make_float2(acc[nt][0], acc[nt][1]);
        if (v1r)
            *reinterpret_cast<float2*>(Hout + (size_t)rowA1 * NOUT + col) =
                make_float2(acc[nt][2], acc[nt][3]);
    }
#pragma unroll
    for (int off = 1; off <= 2; off <<= 1) {
        asum[0] += __shfl_xor_sync(0xffffffffu, asum[0], off);
        asum[1] += __shfl_xor_sync(0xffffffffu, asum[1], off);
        dsum[0] += __shfl_xor_sync(0xffffffffu, dsum[0], off);
        dsum[1] += __shfl_xor_sync(0xffffffffu, dsum[1], off);
    }
    if (j == 0) {
        if (v0r) {
            as_out[(size_t)rowA0 * HEADS + head] = asum[0];
            ad_out[(size_t)rowA0 * HEADS + head] = dsum[0];
        }
        if (v1r) {
            as_out[(size_t)rowA1 * HEADS + head] = asum[1];
            ad_out[(size_t)rowA1 * HEADS + head] = dsum[1];
        }
    }
}

// ---------------- CSR build ----------------
__global__ void deg_count(const int* __restrict__ ei, int* __restrict__ deg, int E) {
    int i = blockIdx.x * blockDim.x + threadIdx.x;
    if (i < E) atomicAdd(&deg[ei[E + i]], 1);
}

__global__ void scan_block(const int* __restrict__ deg, int* __restrict__ incl,
                           int* __restrict__ bsum, int n) {
    __shared__ int wsum[32];
    int tid = threadIdx.x;
    int lane = tid & 31;
    int wid = tid >> 5;
    int gid = blockIdx.x * 1024 + tid;
    int v = (gid < n) ? deg[gid] : 0;
#pragma unroll
    for (int off = 1; off < 32; off <<= 1) {
        int t = __shfl_up_sync(0xffffffffu, v, off);
        if (lane >= off) v += t;
    }
    if (lane == 31) wsum[wid] = v;
    __syncthreads();
    if (wid == 0) {
        int w = wsum[lane];
#pragma unroll
        for (int off = 1; off < 32; off <<= 1) {
            int t = __shfl_up_sync(0xffffffffu, w, off);
            if (lane >= off) w += t;
        }
        wsum[lane] = w;
    }
    __syncthreads();
    if (wid > 0) v += wsum[wid - 1];
    if (gid < n) incl[gid] = v;
    if (tid == 1023) bsum[blockIdx.x] = v;
}

__global__ void scan_finish(const int* __restrict__ incl, const int* __restrict__ bsum,
                            const int* __restrict__ deg, int* __restrict__ rowptr,
                            int* __restrict__ cursor, int n, int nb) {
    __shared__ int pre[128];
    int tid = threadIdx.x;
    if (tid < 32) {
        int base = tid * 4;
        int v[4];
#pragma unroll
        for (int q = 0; q < 4; q++) v[q] = (base + q < nb) ? bsum[base + q] : 0;
        int tot = v[0] + v[1] + v[2] + v[3];
        int inc = tot;
#pragma unroll
        for (int off = 1; off < 32; off <<= 1) {
            int t = __shfl_up_sync(0xffffffffu, inc, off);
            if (tid >= off) inc += t;
        }
        int run = inc - tot;
#pragma unroll
        for (int q = 0; q < 4; q++) {
            pre[base + q] = run;
            run += v[q];
        }
    }
    __syncthreads();
    int i = blockIdx.x * blockDim.x + tid;
    if (i < n) {
        int end = incl[i] + pre[i >> 10];
        rowptr[i + 1] = end;
        cursor[i] = end - deg[i];
    }
    if (i == 0) rowptr[0] = 0;
}

__global__ void scatter_edges(const int* __restrict__ ei, int* __restrict__ cursor,
                              int* __restrict__ adj, int E, int n) {
    int i = blockIdx.x * blockDim.x + threadIdx.x;
    if (i >= E + n) return;
    int s;
    int d;
    if (i < E) {
        s = ei[i];
        d = ei[E + i];
    } else {
        s = i - E;
        d = s;
    }
    int pos = atomicAdd(&cursor[d], 1);
    adj[pos] = s;
}

// ---------------- layer1 node aggregation ----------------
__global__ void gat_node1(const int* __restrict__ rowptr, const int* __restrict__ adj,
                          const float* __restrict__ as, const float* __restrict__ ad,
                          const float* __restrict__ h, const float* __restrict__ b,
                          float* __restrict__ out, int n) {
    int node = (blockIdx.x * blockDim.x + threadIdx.x) >> 5;
    int lane = threadIdx.x & 31;
    if (node >= n) return;
    int start = rowptr[node];
    int end = rowptr[node + 1];
    float ad0 = ad[node * 2];
    float ad1 = ad[node * 2 + 1];
    bool hi = lane >= 16;

    float4 acc = make_float4(0.f, 0.f, 0.f, 0.f);
    float den0 = 0.f;
    float den1 = 0.f;
    for (int base = start; base < end; base += 32) {
        int cnt = min(32, end - base);
        int s_l = 0;
        float ex0_l = 0.f;
        float ex1_l = 0.f;
        if (lane < cnt) {
            s_l = adj[base + lane];
            float e0 = as[s_l * 2] + ad0;
            e0 = e0 >= 0.f ? e0 : 0.2f * e0;
            float e1 = as[s_l * 2 + 1] + ad1;
            e1 = e1 >= 0.f ? e1 : 0.2f * e1;
            ex0_l = expf(e0);
            ex1_l = expf(e1);
        }
        den0 += ex0_l;
        den1 += ex1_l;
#pragma unroll 4
        for (int tt = 0; tt < cnt; tt++) {
            int s = __shfl_sync(0xffffffffu, s_l, tt);
            float ex0 = __shfl_sync(0xffffffffu, ex0_l, tt);
            float ex1 = __shfl_sync(0xffffffffu, ex1_l, tt);
            float ex = hi ? ex1 : ex0;
            float4 v = reinterpret_cast<const float4*>(h + (size_t)s * 128)[lane];
            acc.x = fmaf(ex, v.x, acc.x);
            acc.y = fmaf(ex, v.y, acc.y);
            acc.z = fmaf(ex, v.z, acc.z);
            acc.w = fmaf(ex, v.w, acc.w);
        }
    }
    for (int o = 16; o > 0; o >>= 1) {
        den0 += __shfl_xor_sync(0xffffffffu, den0, o);
        den1 += __shfl_xor_sync(0xffffffffu, den1, o);
    }
    float den = fmaxf(hi ? den1 : den0, 1e-16f);
    float inv = 1.f / den;
    float4 bb = reinterpret_cast<const float4*>(b)[lane];
    float4 o;
    o.x = fmaxf(fmaf(acc.x, inv, bb.x), 0.f);
    o.y = fmaxf(fmaf(acc.y, inv, bb.y), 0.f);
    o.z = fmaxf(fmaf(acc.z, inv, bb.z), 0.f);
    o.w = fmaxf(fmaf(acc.w, inv, bb.w), 0.f);
    reinterpret_cast<float4*>(out + (size_t)node * 128)[lane] = o;
}

// ---------------- layer2 node aggregation ----------------
__global__ void gat_node2(const int* __restrict__ rowptr, const int* __restrict__ adj,
                          const float* __restrict__ as, const float* __restrict__ ad,
                          const float* __restrict__ h, const float* __restrict__ b,
                          float* __restrict__ out, int n) {
    int node = (blockIdx.x * blockDim.x + threadIdx.x) >> 5;
    int lane = threadIdx.x & 31;
    if (node >= n) return;
    int start = rowptr[node];
    int end = rowptr[node + 1];
    float add = ad[node];

    float2 acc = make_float2(0.f, 0.f);
    float den = 0.f;
    for (int base = start; base < end; base += 32) {
        int cnt = min(32, end - base);
        int s_l = 0;
        float ex_l = 0.f;
        if (lane < cnt) {
            s_l = adj[base + lane];
            float e = as[s_l] + add;
            e = e >= 0.f ? e : 0.2f * e;
            ex_l = expf(e);
        }
        den += ex_l;
#pragma unroll 4
        for (int tt = 0; tt < cnt; tt++) {
            int s = __shfl_sync(0xffffffffu, s_l, tt);
            float ex = __shfl_sync(0xffffffffu, ex_l, tt);
            float2 v = reinterpret_cast<const float2*>(h + (size_t)s * 64)[lane];
            acc.x = fmaf(ex, v.x, acc.x);
            acc.y = fmaf(ex, v.y, acc.y);
        }
    }
    for (int o = 16; o > 0; o >>= 1) {
        den += __shfl_xor_sync(0xffffffffu, den, o);
    }
    float inv = 1.f / fmaxf(den, 1e-16f);
    float2 bb = reinterpret_cast<const float2*>(b)[lane];
    float2 o;
    o.x = fmaf(acc.x, inv, bb.x);
    o.y = fmaf(acc.y, inv, bb.y);
    reinterpret_cast<float2*>(out + (size_t)node * 64)[lane] = o;
}

// ---------------- per-graph pooling (batch sorted) ----------------
__global__ void pool_seg(const float* __restrict__ h, const int* __restrict__ batch,
                         float* __restrict__ psum, float* __restrict__ pmax,
                         float* __restrict__ cnt, int n) {
    int n0 = blockIdx.x * 128;
    int t = threadIdx.x;
    int c = t & 63;
    int off = t >> 6;
    int gcur = -1;
    float sum = 0.f;
    float mx = -FLT_MAX;
    float count = 0.f;
    int lim = min(n0 + 128, n);
    for (int i = n0 + off; i < lim; i += 4) {
        int g = batch[i];
        if (g != gcur) {
            if (gcur >= 0) {
                atomicAdd(&psum[gcur * 64 + c], sum);
                atomicMaxF(&pmax[gcur * 64 + c], mx);
                if (c == 0) atomicAdd(&cnt[gcur], count);
            }
            gcur = g;
            sum = 0.f;
            mx = -FLT_MAX;
            count = 0.f;
        }
        float v = h[(size_t)i * 64 + c];
        sum += v;
        mx = fmaxf(mx, v);
        count += 1.f;
    }
    if (gcur >= 0) {
        atomicAdd(&psum[gcur * 64 + c], sum);
        atomicMaxF(&pmax[gcur * 64 + c], mx);
        if (c == 0) atomicAdd(&cnt[gcur], count);
    }
}

// ---------------- final MLP head ----------------
__global__ void final_mlp_kernel(const float* __restrict__ psum, const float* __restrict__ pmax,
                                 const float* __restrict__ cnt, const float* __restrict__ Wf1,
                                 const float* __restrict__ bf1, const float* __restrict__ Wf2,
                                 const float* __restrict__ bf2, float* __restrict__ out) {
    __shared__ float pooled[128];
    __shared__ float red[64];
    int g = blockIdx.x;
    int t = threadIdx.x;
    float c = cnt[g];
    pooled[t] = psum[g * 64 + t] / fmaxf(c, 1.f);
    pooled[64 + t] = (c > 0.f) ? pmax[g * 64 + t] : 0.f;
    __syncthreads();
    float hj = bf1[t];
    for (int k = 0; k < 128; k++) {
        hj = fmaf(pooled[k], Wf1[k * 64 + t], hj);
    }
    hj = fmaxf(hj, 0.f);
    red[t] = hj * Wf2[t];
    __syncthreads();
    for (int s = 32; s > 0; s >>= 1) {
        if (t < s) red[t] += red[t + s];
        __syncthreads();
    }
    if (t == 0) out[g] = red[0] + bf2[0];
}

// ---------------- host launch ----------------
static inline int cdiv(int a, int b) { return (a + b - 1) / b; }

extern "C" void kernel_launch(void* const* d_in, const int* in_sizes, int n_in,
                              void* d_out, int out_size) {
    const float* x = (const float*)d_in[0];
    const int* ei = (const int*)d_in[1];
    const int* bat = (const int*)d_in[2];
    const float* W1 = (const float*)d_in[3];
    const float* as1 = (const float*)d_in[4];
    const float* ad1 = (const float*)d_in[5];
    const float* b1 = (const float*)d_in[6];
    const float* W2 = (const float*)d_in[7];
    const float* as2 = (const float*)d_in[8];
    const float* ad2 = (const float*)d_in[9];
    const float* b2 = (const float*)d_in[10];
    const float* Wf1 = (const float*)d_in[11];
    const float* bf1 = (const float*)d_in[12];
    const float* Wf2 = (const float*)d_in[13];
    const float* bf2 = (const float*)d_in[14];
    float* out = (float*)d_out;

    const int n = in_sizes[0] / 128;
    const int E = in_sizes[1] / 2;
    const int G = out_size;

    float* p_h1;
    float* p_o1;
    float* p_h2;
    float* p_o2;
    float* p_as1;
    float* p_ad1;
    float* p_as2;
    float* p_ad2;
    float* p_psum;
    float* p_pmax;
    float* p_cnt;
    int* p_deg;
    int* p_incl;
    int* p_bsum;
    int* p_rowptr;
    int* p_cursor;
    int* p_adj;
    uint32_t* p_w1pk;
    uint32_t* p_w2pk;
    cudaGetSymbolAddress((void**)&p_h1, g_h1);
    cudaGetSymbolAddress((void**)&p_o1, g_o1);
    cudaGetSymbolAddress((void**)&p_h2, g_h2);
    cudaGetSymbolAddress((void**)&p_o2, g_o2);
    cudaGetSymbolAddress((void**)&p_as1, g_as1);
    cudaGetSymbolAddress((void**)&p_ad1, g_ad1);
    cudaGetSymbolAddress((void**)&p_as2, g_as2);
    cudaGetSymbolAddress((void**)&p_ad2, g_ad2);
    cudaGetSymbolAddress((void**)&p_psum, g_psum);
    cudaGetSymbolAddress((void**)&p_pmax, g_pmax);
    cudaGetSymbolAddress((void**)&p_cnt, g_cnt);
    cudaGetSymbolAddress((void**)&p_deg, g_deg);
    cudaGetSymbolAddress((void**)&p_incl, g_incl);
    cudaGetSymbolAddress((void**)&p_bsum, g_bsum);
    cudaGetSymbolAddress((void**)&p_rowptr, g_rowptr);
    cudaGetSymbolAddress((void**)&p_cursor, g_cursor);
    cudaGetSymbolAddress((void**)&p_adj, g_adj);
    cudaGetSymbolAddress((void**)&p_w1pk, g_w1pk);
    cudaGetSymbolAddress((void**)&p_w2pk, g_w2pk);

    const int TB = 256;
    const int nb = cdiv(n, 1024);

    const int SMEMH = 512 + 64 * 576;  // 37376
    cudaFuncSetAttribute(gemm_head<2>, cudaFuncAttributeMaxDynamicSharedMemorySize, SMEMH);
    cudaFuncSetAttribute(gemm_head<1>, cudaFuncAttributeMaxDynamicSharedMemorySize, SMEMH);

    static cudaStream_t s2 = nullptr;
    static cudaEvent_t evA = nullptr;
    static cudaEvent_t evB = nullptr;
    if (s2 == nullptr) {
        cudaStreamCreateWithFlags(&s2, cudaStreamNonBlocking);
        cudaEventCreateWithFlags(&evA, cudaEventDisableTiming);
        cudaEventCreateWithFlags(&evB, cudaEventDisableTiming);
    }

    // launch 0: setup (packed weights + deg init + pool fills)
    setup_kernel<<<cdiv(n, TB), TB>>>(W1, W2, p_w1pk, p_w2pk, p_deg, p_psum, p_pmax, p_cnt, n, G);

    // fork CSR chain to side stream
    cudaEventRecord(evA, 0);
    cudaStreamWaitEvent(s2, evA, 0);
    deg_count<<<cdiv(E, TB), TB, 0, s2>>>(ei, p_deg, E);        // launch 1
    scan_block<<<nb, 1024, 0, s2>>>(p_deg, p_incl, p_bsum, n);  // launch 2

    // launch 3 (profiled slot): layer-1 GEMM on main stream
    dim3 grid1(cdiv(n, 128), 2);
    gemm_head<2><<<grid1, 256, SMEMH>>>(x, p_w1pk, as1, ad1, p_h1, p_as1, p_ad1, n);

    scan_finish<<<cdiv(n, TB), TB, 0, s2>>>(p_incl, p_bsum, p_deg, p_rowptr, p_cursor, n, nb);
    scatter_edges<<<cdiv(E + n, TB), TB, 0, s2>>>(ei, p_cursor, p_adj, E, n);
    cudaEventRecord(evB, s2);

    // join: gat_node1 needs gemm1 + CSR
    cudaStreamWaitEvent(0, evB, 0);
    gat_node1<<<cdiv(n * 32, TB), TB>>>(p_rowptr, p_adj, p_as1, p_ad1, p_h1, b1, p_o1, n);

    // layer 2
    dim3 grid2(cdiv(n, 128), 1);
    gemm_head<1><<<grid2, 256, SMEMH>>>(p_o1, p_w2pk, as2, ad2, p_h2, p_as2, p_ad2, n);
    gat_node2<<<cdiv(n * 32, TB), TB>>>(p_rowptr, p_adj, p_as2, p_ad2, p_h2, b2, p_o2, n);

    // pooling + head
    pool_seg<<<cdiv(n, 128), 256>>>(p_o2, bat, p_psum, p_pmax, p_cnt, n);
    final_mlp_kernel<<<G, 64>>>(p_psum, p_pmax, p_cnt, Wf1, bf1, Wf2, bf2, out);
}

// round 13
// speedup vs baseline: 1.0959x; 1.0959x over previous
#include <cuda_runtime.h>
#include <cuda_bf16.h>
#include <cuda_fp16.h>
#include <cstdint>
#include <stdint.h>
#include <float.h>
#include <math.h>

#define MAX_NODES 100000
#define MAX_EDGES 600000
#define MAX_GRAPHS 512

// ---------------- scratch (device globals) ----------------
__device__ __half g_h1[(size_t)MAX_NODES * 128];  // layer1 features (fp16, gather-only)
__device__ float g_o1[(size_t)MAX_NODES * 128];
__device__ __half g_h2[(size_t)MAX_NODES * 64];   // layer2 features (fp16, gather-only)
__device__ float g_o2[(size_t)MAX_NODES * 64];
__device__ float g_as1[MAX_NODES * 2];
__device__ float g_ad1[MAX_NODES * 2];
__device__ float g_as2[MAX_NODES];
__device__ float g_ad2[MAX_NODES];
// fragment-packed weights: word idx = ((n*8+ks)*4+j)*4 + {hi_k, hi_k8, lo_k, lo_k8}
__device__ uint32_t g_w1pk[128 * 128];
__device__ uint32_t g_w2pk[64 * 128];
__device__ int g_deg[MAX_NODES];
__device__ int g_incl[MAX_NODES];
__device__ int g_bsum[256];
__device__ int g_rowptr[MAX_NODES + 1];
__device__ int g_cursor[MAX_NODES];
__device__ int g_adj[MAX_EDGES + MAX_NODES];
__device__ float g_psum[MAX_GRAPHS * 64];
__device__ float g_pmax[MAX_GRAPHS * 64];
__device__ float g_cnt[MAX_GRAPHS];

// ---------------- misc ----------------
__device__ __forceinline__ void atomicMaxF(float* addr, float value) {
    if (value >= 0.f) {
        atomicMax((int*)addr, __float_as_int(value));
    } else {
        atomicMin((unsigned int*)addr, __float_as_uint(value));
    }
}

__device__ __forceinline__ void mma_bf16(float* d, const uint32_t* a, uint32_t b0, uint32_t b1) {
    asm volatile(
        "mma.sync.aligned.m16n8k16.row.col.f32.bf16.bf16.f32 "
        "{%0, %1, %2, %3}, {%4, %5, %6, %7}, {%8, %9}, {%0, %1, %2, %3};"
        : "+f"(d[0]), "+f"(d[1]), "+f"(d[2]), "+f"(d[3])
        : "r"(a[0]), "r"(a[1]), "r"(a[2]), "r"(a[3]), "r"(b0), "r"(b1));
}

__device__ __forceinline__ void cvt_hilo(float2 x, uint32_t& hi, uint32_t& lo) {
    __nv_bfloat16 h0 = __float2bfloat16(x.x);
    __nv_bfloat16 h1 = __float2bfloat16(x.y);
    __nv_bfloat16 l0 = __float2bfloat16(x.x - __bfloat162float(h0));
    __nv_bfloat16 l1 = __float2bfloat16(x.y - __bfloat162float(h1));
    hi = (uint32_t)__bfloat16_as_ushort(h0) | ((uint32_t)__bfloat16_as_ushort(h1) << 16);
    lo = (uint32_t)__bfloat16_as_ushort(l0) | ((uint32_t)__bfloat16_as_ushort(l1) << 16);
}

// ---------------- setup: deg=1 + fragment-packed weight preps + pool fills ----------------
__global__ void setup_kernel(const float* __restrict__ W1, const float* __restrict__ W2,
                             uint32_t* __restrict__ w1pk, uint32_t* __restrict__ w2pk,
                             int* __restrict__ deg, float* __restrict__ psum,
                             float* __restrict__ pmax, float* __restrict__ cnt, int n, int gtot) {
    int idx = blockIdx.x * blockDim.x + threadIdx.x;
    if (idx < n) deg[idx] = 1;
    if (idx < 128 * 64) {
        int nr = idx >> 6;
        int p = idx & 63;
        int k0 = p * 2;
        int ks = k0 >> 4;
        int r = k0 & 15;
        int halfk = r >> 3;
        int j = (r & 7) >> 1;
        float2 v = make_float2(W1[k0 * 128 + nr], W1[(k0 + 1) * 128 + nr]);
        uint32_t hw;
        uint32_t lw;
        cvt_hilo(v, hw, lw);
        int base = ((nr * 8 + ks) * 4 + j) * 4;
        w1pk[base + halfk] = hw;
        w1pk[base + 2 + halfk] = lw;
    }
    if (idx < 64 * 64) {
        int nr = idx >> 6;
        int p = idx & 63;
        int k0 = p * 2;
        int ks = k0 >> 4;
        int r = k0 & 15;
        int halfk = r >> 3;
        int j = (r & 7) >> 1;
        float2 v = make_float2(W2[k0 * 64 + nr], W2[(k0 + 1) * 64 + nr]);
        uint32_t hw;
        uint32_t lw;
        cvt_hilo(v, hw, lw);
        int base = ((nr * 8 + ks) * 4 + j) * 4;
        w2pk[base + halfk] = hw;
        w2pk[base + 2 + halfk] = lw;
    }
    if (idx < gtot * 64) {
        psum[idx] = 0.f;
        pmax[idx] = -FLT_MAX;
    }
    if (idx < gtot) cnt[idx] = 0.f;
}

// ---------------- layer-1 HMMA GEMM: warp = 32 rows x 8 n-tiles (one head) ----------------
// C[n,128] = A[n,128] @ W; 128 rows/CTA; 8 warps = 4 rowgrps x 2 colgrps.
// H output stored fp16 (gather-only consumer).
__global__ __launch_bounds__(256, 2) void gemm_mma1(
    const float* __restrict__ A, const uint32_t* __restrict__ Wpk,
    const float* __restrict__ avs, const float* __restrict__ avd, __half* __restrict__ Hout,
    float* __restrict__ as_out, float* __restrict__ ad_out, int n) {
    extern __shared__ __align__(16) char sm[];
    constexpr int WST = 576;
    const uint32_t OFF_AVS = 0;
    const uint32_t OFF_AVD = 512;
    const uint32_t OFF_W = 1024;

    const int tid = threadIdx.x;
    const int row0 = blockIdx.x * 128;

    if (tid < 128) {
        reinterpret_cast<float*>(sm + OFF_AVS)[tid] = avs[tid];
        reinterpret_cast<float*>(sm + OFF_AVD)[tid] = avd[tid];
    }
    {
        const uint4* wsrc = reinterpret_cast<const uint4*>(Wpk);
#pragma unroll
        for (int i = tid; i < 128 * 32; i += 256) {
            int nr = i >> 5;
            int w = i & 31;
            *reinterpret_cast<uint4*>(sm + OFF_W + nr * WST + w * 16) = wsrc[i];
        }
    }
    __syncthreads();

    const int warp = tid >> 5;
    const int lane = tid & 31;
    const int g = lane >> 2;
    const int j = lane & 3;
    const int rowgrp = warp >> 1;
    const int colgrp = warp & 1;

    const int r0 = row0 + rowgrp * 32 + g;
    const bool v0 = (r0 < n);
    const bool v1 = (r0 + 8 < n);
    const bool v2 = (r0 + 16 < n);
    const bool v3 = (r0 + 24 < n);
    const float* ap0 = A + (size_t)r0 * 128 + j * 2;
    const float* ap1 = ap0 + 8 * 128;
    const float* ap2 = ap0 + 16 * 128;
    const float* ap3 = ap0 + 24 * 128;

    float acc0[8][4];
    float acc1[8][4];
#pragma unroll
    for (int nt = 0; nt < 8; nt++)
#pragma unroll
        for (int q = 0; q < 4; q++) {
            acc0[nt][q] = 0.f;
            acc1[nt][q] = 0.f;
        }

    const char* bw = sm + OFF_W + (colgrp * 64 + g) * WST + j * 16;
    const float2 z2 = make_float2(0.f, 0.f);
#pragma unroll
    for (int ks = 0; ks < 8; ks++) {
        float2 x00 = v0 ? *reinterpret_cast<const float2*>(ap0 + ks * 16) : z2;
        float2 x01 = v0 ? *reinterpret_cast<const float2*>(ap0 + ks * 16 + 8) : z2;
        float2 x10 = v1 ? *reinterpret_cast<const float2*>(ap1 + ks * 16) : z2;
        float2 x11 = v1 ? *reinterpret_cast<const float2*>(ap1 + ks * 16 + 8) : z2;
        float2 x20 = v2 ? *reinterpret_cast<const float2*>(ap2 + ks * 16) : z2;
        float2 x21 = v2 ? *reinterpret_cast<const float2*>(ap2 + ks * 16 + 8) : z2;
        float2 x30 = v3 ? *reinterpret_cast<const float2*>(ap3 + ks * 16) : z2;
        float2 x31 = v3 ? *reinterpret_cast<const float2*>(ap3 + ks * 16 + 8) : z2;
        uint32_t ahi0[4];
        uint32_t alo0[4];
        uint32_t ahi1[4];
        uint32_t alo1[4];
        cvt_hilo(x00, ahi0[0], alo0[0]);
        cvt_hilo(x10, ahi0[1], alo0[1]);
        cvt_hilo(x01, ahi0[2], alo0[2]);
        cvt_hilo(x11, ahi0[3], alo0[3]);
        cvt_hilo(x20, ahi1[0], alo1[0]);
        cvt_hilo(x30, ahi1[1], alo1[1]);
        cvt_hilo(x21, ahi1[2], alo1[2]);
        cvt_hilo(x31, ahi1[3], alo1[3]);
        const char* bks = bw + ks * 64;
#pragma unroll
        for (int nt = 0; nt < 8; nt++) {
            uint4 b = *reinterpret_cast<const uint4*>(bks + nt * 8 * WST);
            mma_bf16(acc0[nt], ahi0, b.x, b.y);
            mma_bf16(acc0[nt], ahi0, b.z, b.w);
            mma_bf16(acc0[nt], alo0, b.x, b.y);
            mma_bf16(acc1[nt], ahi1, b.x, b.y);
            mma_bf16(acc1[nt], ahi1, b.z, b.w);
            mma_bf16(acc1[nt], alo1, b.x, b.y);
        }
    }

    const float* avs_s = reinterpret_cast<const float*>(sm + OFF_AVS);
    const float* avd_s = reinterpret_cast<const float*>(sm + OFF_AVD);
    float as[4] = {0.f, 0.f, 0.f, 0.f};
    float ds[4] = {0.f, 0.f, 0.f, 0.f};
#pragma unroll
    for (int nt = 0; nt < 8; nt++) {
        int cn = colgrp * 64 + nt * 8 + 2 * j;
        float av0 = avs_s[cn];
        float av1 = avs_s[cn + 1];
        float dv0 = avd_s[cn];
        float dv1 = avd_s[cn + 1];
        as[0] += acc0[nt][0] * av0 + acc0[nt][1] * av1;
        as[1] += acc0[nt][2] * av0 + acc0[nt][3] * av1;
        as[2] += acc1[nt][0] * av0 + acc1[nt][1] * av1;
        as[3] += acc1[nt][2] * av0 + acc1[nt][3] * av1;
        ds[0] += acc0[nt][0] * dv0 + acc0[nt][1] * dv1;
        ds[1] += acc0[nt][2] * dv0 + acc0[nt][3] * dv1;
        ds[2] += acc1[nt][0] * dv0 + acc1[nt][1] * dv1;
        ds[3] += acc1[nt][2] * dv0 + acc1[nt][3] * dv1;
        if (v0)
            *reinterpret_cast<__half2*>(Hout + (size_t)r0 * 128 + cn) =
                __floats2half2_rn(acc0[nt][0], acc0[nt][1]);
        if (v1)
            *reinterpret_cast<__half2*>(Hout + (size_t)(r0 + 8) * 128 + cn) =
                __floats2half2_rn(acc0[nt][2], acc0[nt][3]);
        if (v2)
            *reinterpret_cast<__half2*>(Hout + (size_t)(r0 + 16) * 128 + cn) =
                __floats2half2_rn(acc1[nt][0], acc1[nt][1]);
        if (v3)
            *reinterpret_cast<__half2*>(Hout + (size_t)(r0 + 24) * 128 + cn) =
                __floats2half2_rn(acc1[nt][2], acc1[nt][3]);
    }
#pragma unroll
    for (int off = 1; off <= 2; off <<= 1) {
#pragma unroll
        for (int q = 0; q < 4; q++) {
            as[q] += __shfl_xor_sync(0xffffffffu, as[q], off);
            ds[q] += __shfl_xor_sync(0xffffffffu, ds[q], off);
        }
    }
    if (j == 0) {
        const bool vr[4] = {v0, v1, v2, v3};
#pragma unroll
        for (int q = 0; q < 4; q++) {
            if (vr[q]) {
                int r = r0 + q * 8;
                as_out[(size_t)r * 2 + colgrp] = as[q];
                ad_out[(size_t)r * 2 + colgrp] = ds[q];
            }
        }
    }
}

// ---------------- layer-2 HMMA GEMM (NOUT=64, fp16 H output) ----------------
__global__ __launch_bounds__(256, 2) void gemm_mma2(
    const float* __restrict__ A, const uint32_t* __restrict__ Wpk,
    const float* __restrict__ avs, const float* __restrict__ avd, __half* __restrict__ Hout,
    float* __restrict__ as_out, float* __restrict__ ad_out, int n) {
    extern __shared__ __align__(16) char sm[];
    constexpr int NOUT = 64;
    constexpr int NT = 8;
    constexpr int WST = 576;
    const uint32_t OFF_AVS = 0;
    const uint32_t OFF_AVD = 512;
    const uint32_t OFF_W = 1024;

    const int tid = threadIdx.x;
    const int row0 = blockIdx.x * 128;

    if (tid < NOUT) {
        reinterpret_cast<float*>(sm + OFF_AVS)[tid] = avs[tid];
        reinterpret_cast<float*>(sm + OFF_AVD)[tid] = avd[tid];
    }
    {
        const uint4* wsrc = reinterpret_cast<const uint4*>(Wpk);
#pragma unroll
        for (int i = tid; i < NOUT * 32; i += 256) {
            int nr = i >> 5;
            int w = i & 31;
            *reinterpret_cast<uint4*>(sm + OFF_W + nr * WST + w * 16) = wsrc[i];
        }
    }
    __syncthreads();

    const int warp = tid >> 5;
    const int lane = tid & 31;
    const int g = lane >> 2;
    const int j = lane & 3;
    const int wm0 = warp * 16;

    const int rowA0 = row0 + wm0 + g;
    const int rowA1 = rowA0 + 8;
    const bool v0r = rowA0 < n;
    const bool v1r = rowA1 < n;
    const float* a0p = A + (size_t)rowA0 * 128 + j * 2;
    const float* a1p = A + (size_t)rowA1 * 128 + j * 2;

    float acc[NT][4];
#pragma unroll
    for (int nt = 0; nt < NT; nt++)
#pragma unroll
        for (int q = 0; q < 4; q++) acc[nt][q] = 0.f;

    const char* bw = sm + OFF_W + g * WST + j * 16;
    const float2 z2 = make_float2(0.f, 0.f);
#pragma unroll
    for (int ks = 0; ks < 8; ks++) {
        float2 x00 = v0r ? *reinterpret_cast<const float2*>(a0p + ks * 16) : z2;
        float2 x01 = v0r ? *reinterpret_cast<const float2*>(a0p + ks * 16 + 8) : z2;
        float2 x10 = v1r ? *reinterpret_cast<const float2*>(a1p + ks * 16) : z2;
        float2 x11 = v1r ? *reinterpret_cast<const float2*>(a1p + ks * 16 + 8) : z2;
        uint32_t ahi[4];
        uint32_t alo[4];
        cvt_hilo(x00, ahi[0], alo[0]);
        cvt_hilo(x10, ahi[1], alo[1]);
        cvt_hilo(x01, ahi[2], alo[2]);
        cvt_hilo(x11, ahi[3], alo[3]);
        const char* bks = bw + ks * 64;
#pragma unroll
        for (int nt = 0; nt < NT; nt++) {
            uint4 b = *reinterpret_cast<const uint4*>(bks + nt * 8 * WST);
            mma_bf16(acc[nt], ahi, b.x, b.y);
            mma_bf16(acc[nt], ahi, b.z, b.w);
            mma_bf16(acc[nt], alo, b.x, b.y);
        }
    }

    const float* avs_s = reinterpret_cast<const float*>(sm + OFF_AVS);
    const float* avd_s = reinterpret_cast<const float*>(sm + OFF_AVD);
    float asum[2] = {0.f, 0.f};
    float dsum[2] = {0.f, 0.f};
#pragma unroll
    for (int nt = 0; nt < NT; nt++) {
        int cn = nt * 8 + 2 * j;
        float av0 = avs_s[cn];
        float av1 = avs_s[cn + 1];
        float dv0 = avd_s[cn];
        float dv1 = avd_s[cn + 1];
        asum[0] += acc[nt][0] * av0 + acc[nt][1] * av1;
        asum[1] += acc[nt][2] * av0 + acc[nt][3] * av1;
        dsum[0] += acc[nt][0] * dv0 + acc[nt][1] * dv1;
        dsum[1] += acc[nt][2] * dv0 + acc[nt][3] * dv1;
        if (v0r)
            *reinterpret_cast<__half2*>(Hout + (size_t)rowA0 * NOUT + cn) =
                __floats2half2_rn(acc[nt][0], acc[nt][1]);
        if (v1r)
            *reinterpret_cast<__half2*>(Hout + (size_t)rowA1 * NOUT + cn) =
                __floats2half2_rn(acc[nt][2], acc[nt][3]);
    }
#pragma unroll
    for (int off = 1; off <= 2; off <<= 1) {
        asum[0] += __shfl_xor_sync(0xffffffffu, asum[0], off);
        asum[1] += __shfl_xor_sync(0xffffffffu, asum[1], off);
        dsum[0] += __shfl_xor_sync(0xffffffffu, dsum[0], off);
        dsum[1] += __shfl_xor_sync(0xffffffffu, dsum[1], off);
    }
    if (j == 0) {
        if (v0r) {
            as_out[rowA0] = asum[0];
            ad_out[rowA0] = dsum[0];
        }
        if (v1r) {
            as_out[rowA1] = asum[1];
            ad_out[rowA1] = dsum[1];
        }
    }
}

// ---------------- CSR build ----------------
__global__ void deg_count(const int* __restrict__ ei, int* __restrict__ deg, int E) {
    int i = blockIdx.x * blockDim.x + threadIdx.x;
    if (i < E) atomicAdd(&deg[ei[E + i]], 1);
}

__global__ void scan_block(const int* __restrict__ deg, int* __restrict__ incl,
                           int* __restrict__ bsum, int n) {
    __shared__ int wsum[32];
    int tid = threadIdx.x;
    int lane = tid & 31;
    int wid = tid >> 5;
    int gid = blockIdx.x * 1024 + tid;
    int v = (gid < n) ? deg[gid] : 0;
#pragma unroll
    for (int off = 1; off < 32; off <<= 1) {
        int t = __shfl_up_sync(0xffffffffu, v, off);
        if (lane >= off) v += t;
    }
    if (lane == 31) wsum[wid] = v;
    __syncthreads();
    if (wid == 0) {
        int w = wsum[lane];
#pragma unroll
        for (int off = 1; off < 32; off <<= 1) {
            int t = __shfl_up_sync(0xffffffffu, w, off);
            if (lane >= off) w += t;
        }
        wsum[lane] = w;
    }
    __syncthreads();
    if (wid > 0) v += wsum[wid - 1];
    if (gid < n) incl[gid] = v;
    if (tid == 1023) bsum[blockIdx.x] = v;
}

__global__ void scan_finish(const int* __restrict__ incl, const int* __restrict__ bsum,
                            const int* __restrict__ deg, int* __restrict__ rowptr,
                            int* __restrict__ cursor, int n, int nb) {
    __shared__ int pre[128];
    int tid = threadIdx.x;
    if (tid < 32) {
        int base = tid * 4;
        int v[4];
#pragma unroll
        for (int q = 0; q < 4; q++) v[q] = (base + q < nb) ? bsum[base + q] : 0;
        int tot = v[0] + v[1] + v[2] + v[3];
        int inc = tot;
#pragma unroll
        for (int off = 1; off < 32; off <<= 1) {
            int t = __shfl_up_sync(0xffffffffu, inc, off);
            if (tid >= off) inc += t;
        }
        int run = inc - tot;
#pragma unroll
        for (int q = 0; q < 4; q++) {
            pre[base + q] = run;
            run += v[q];
        }
    }
    __syncthreads();
    int i = blockIdx.x * blockDim.x + tid;
    if (i < n) {
        int end = incl[i] + pre[i >> 10];
        rowptr[i + 1] = end;
        cursor[i] = end - deg[i];
    }
    if (i == 0) rowptr[0] = 0;
}

__global__ void scatter_edges(const int* __restrict__ ei, int* __restrict__ cursor,
                              int* __restrict__ adj, int E, int n) {
    int i = blockIdx.x * blockDim.x + threadIdx.x;
    if (i >= E + n) return;
    int s;
    int d;
    if (i < E) {
        s = ei[i];
        d = ei[E + i];
    } else {
        s = i - E;
        d = s;
    }
    int pos = atomicAdd(&cursor[d], 1);
    adj[pos] = s;
}

// ---------------- layer1 node aggregation (fp16 gather) ----------------
__global__ void gat_node1(const int* __restrict__ rowptr, const int* __restrict__ adj,
                          const float* __restrict__ as, const float* __restrict__ ad,
                          const __half* __restrict__ h, const float* __restrict__ b,
                          float* __restrict__ out, int n) {
    int node = (blockIdx.x * blockDim.x + threadIdx.x) >> 5;
    int lane = threadIdx.x & 31;
    if (node >= n) return;
    int start = rowptr[node];
    int end = rowptr[node + 1];
    float ad0 = ad[node * 2];
    float ad1 = ad[node * 2 + 1];
    bool hi = lane >= 16;

    float4 acc = make_float4(0.f, 0.f, 0.f, 0.f);
    float den0 = 0.f;
    float den1 = 0.f;
    for (int base = start; base < end; base += 32) {
        int cnt = min(32, end - base);
        int s_l = 0;
        float ex0_l = 0.f;
        float ex1_l = 0.f;
        if (lane < cnt) {
            s_l = adj[base + lane];
            float e0 = as[s_l * 2] + ad0;
            e0 = e0 >= 0.f ? e0 : 0.2f * e0;
            float e1 = as[s_l * 2 + 1] + ad1;
            e1 = e1 >= 0.f ? e1 : 0.2f * e1;
            ex0_l = expf(e0);
            ex1_l = expf(e1);
        }
        den0 += ex0_l;
        den1 += ex1_l;
#pragma unroll 4
        for (int tt = 0; tt < cnt; tt++) {
            int s = __shfl_sync(0xffffffffu, s_l, tt);
            float ex0 = __shfl_sync(0xffffffffu, ex0_l, tt);
            float ex1 = __shfl_sync(0xffffffffu, ex1_l, tt);
            float ex = hi ? ex1 : ex0;
            uint2 u = reinterpret_cast<const uint2*>(h + (size_t)s * 128)[lane];
            __half2 p0 = *reinterpret_cast<const __half2*>(&u.x);
            __half2 p1 = *reinterpret_cast<const __half2*>(&u.y);
            float2 f0 = __half22float2(p0);
            float2 f1 = __half22float2(p1);
            acc.x = fmaf(ex, f0.x, acc.x);
            acc.y = fmaf(ex, f0.y, acc.y);
            acc.z = fmaf(ex, f1.x, acc.z);
            acc.w = fmaf(ex, f1.y, acc.w);
        }
    }
    for (int o = 16; o > 0; o >>= 1) {
        den0 += __shfl_xor_sync(0xffffffffu, den0, o);
        den1 += __shfl_xor_sync(0xffffffffu, den1, o);
    }
    float den = fmaxf(hi ? den1 : den0, 1e-16f);
    float inv = 1.f / den;
    float4 bb = reinterpret_cast<const float4*>(b)[lane];
    float4 o;
    o.x = fmaxf(fmaf(acc.x, inv, bb.x), 0.f);
    o.y = fmaxf(fmaf(acc.y, inv, bb.y), 0.f);
    o.z = fmaxf(fmaf(acc.z, inv, bb.z), 0.f);
    o.w = fmaxf(fmaf(acc.w, inv, bb.w), 0.f);
    reinterpret_cast<float4*>(out + (size_t)node * 128)[lane] = o;
}

// ---------------- layer2 node aggregation (fp16 gather) ----------------
__global__ void gat_node2(const int* __restrict__ rowptr, const int* __restrict__ adj,
                          const float* __restrict__ as, const float* __restrict__ ad,
                          const __half* __restrict__ h, const float* __restrict__ b,
                          float* __restrict__ out, int n) {
    int node = (blockIdx.x * blockDim.x + threadIdx.x) >> 5;
    int lane = threadIdx.x & 31;
    if (node >= n) return;
    int start = rowptr[node];
    int end = rowptr[node + 1];
    float add = ad[node];

    float2 acc = make_float2(0.f, 0.f);
    float den = 0.f;
    for (int base = start; base < end; base += 32) {
        int cnt = min(32, end - base);
        int s_l = 0;
        float ex_l = 0.f;
        if (lane < cnt) {
            s_l = adj[base + lane];
            float e = as[s_l] + add;
            e = e >= 0.f ? e : 0.2f * e;
            ex_l = expf(e);
        }
        den += ex_l;
#pragma unroll 4
        for (int tt = 0; tt < cnt; tt++) {
            int s = __shfl_sync(0xffffffffu, s_l, tt);
            float ex = __shfl_sync(0xffffffffu, ex_l, tt);
            __half2 p = reinterpret_cast<const __half2*>(h + (size_t)s * 64)[lane];
            float2 f = __half22float2(p);
            acc.x = fmaf(ex, f.x, acc.x);
            acc.y = fmaf(ex, f.y, acc.y);
        }
    }
    for (int o = 16; o > 0; o >>= 1) {
        den += __shfl_xor_sync(0xffffffffu, den, o);
    }
    float inv = 1.f / fmaxf(den, 1e-16f);
    float2 bb = reinterpret_cast<const float2*>(b)[lane];
    float2 o;
    o.x = fmaf(acc.x, inv, bb.x);
    o.y = fmaf(acc.y, inv, bb.y);
    reinterpret_cast<float2*>(out + (size_t)node * 64)[lane] = o;
}

// ---------------- per-graph pooling (batch sorted) ----------------
__global__ void pool_seg(const float* __restrict__ h, const int* __restrict__ batch,
                         float* __restrict__ psum, float* __restrict__ pmax,
                         float* __restrict__ cnt, int n) {
    int n0 = blockIdx.x * 128;
    int t = threadIdx.x;
    int c = t & 63;
    int off = t >> 6;
    int gcur = -1;
    float sum = 0.f;
    float mx = -FLT_MAX;
    float count = 0.f;
    int lim = min(n0 + 128, n);
    for (int i = n0 + off; i < lim; i += 4) {
        int g = batch[i];
        if (g != gcur) {
            if (gcur >= 0) {
                atomicAdd(&psum[gcur * 64 + c], sum);
                atomicMaxF(&pmax[gcur * 64 + c], mx);
                if (c == 0) atomicAdd(&cnt[gcur], count);
            }
            gcur = g;
            sum = 0.f;
            mx = -FLT_MAX;
            count = 0.f;
        }
        float v = h[(size_t)i * 64 + c];
        sum += v;
        mx = fmaxf(mx, v);
        count += 1.f;
    }
    if (gcur >= 0) {
        atomicAdd(&psum[gcur * 64 + c], sum);
        atomicMaxF(&pmax[gcur * 64 + c], mx);
        if (c == 0) atomicAdd(&cnt[gcur], count);
    }
}

// ---------------- final MLP head ----------------
__global__ void final_mlp_kernel(const float* __restrict__ psum, const float* __restrict__ pmax,
                                 const float* __restrict__ cnt, const float* __restrict__ Wf1,
                                 const float* __restrict__ bf1, const float* __restrict__ Wf2,
                                 const float* __restrict__ bf2, float* __restrict__ out) {
    __shared__ float pooled[128];
    __shared__ float red[64];
    int g = blockIdx.x;
    int t = threadIdx.x;
    float c = cnt[g];
    pooled[t] = psum[g * 64 + t] / fmaxf(c, 1.f);
    pooled[64 + t] = (c > 0.f) ? pmax[g * 64 + t] : 0.f;
    __syncthreads();
    float hj = bf1[t];
    for (int k = 0; k < 128; k++) {
        hj = fmaf(pooled[k], Wf1[k * 64 + t], hj);
    }
    hj = fmaxf(hj, 0.f);
    red[t] = hj * Wf2[t];
    __syncthreads();
    for (int s = 32; s > 0; s >>= 1) {
        if (t < s) red[t] += red[t + s];
        __syncthreads();
    }
    if (t == 0) out[g] = red[0] + bf2[0];
}

// ---------------- host launch ----------------
static inline int cdiv(int a, int b) { return (a + b - 1) / b; }

extern "C" void kernel_launch(void* const* d_in, const int* in_sizes, int n_in,
                              void* d_out, int out_size) {
    const float* x = (const float*)d_in[0];
    const int* ei = (const int*)d_in[1];
    const int* bat = (const int*)d_in[2];
    const float* W1 = (const float*)d_in[3];
    const float* as1 = (const float*)d_in[4];
    const float* ad1 = (const float*)d_in[5];
    const float* b1 = (const float*)d_in[6];
    const float* W2 = (const float*)d_in[7];
    const float* as2 = (const float*)d_in[8];
    const float* ad2 = (const float*)d_in[9];
    const float* b2 = (const float*)d_in[10];
    const float* Wf1 = (const float*)d_in[11];
    const float* bf1 = (const float*)d_in[12];
    const float* Wf2 = (const float*)d_in[13];
    const float* bf2 = (const float*)d_in[14];
    float* out = (float*)d_out;

    const int n = in_sizes[0] / 128;
    const int E = in_sizes[1] / 2;
    const int G = out_size;

    __half* p_h1;
    float* p_o1;
    __half* p_h2;
    float* p_o2;
    float* p_as1;
    float* p_ad1;
    float* p_as2;
    float* p_ad2;
    float* p_psum;
    float* p_pmax;
    float* p_cnt;
    int* p_deg;
    int* p_incl;
    int* p_bsum;
    int* p_rowptr;
    int* p_cursor;
    int* p_adj;
    uint32_t* p_w1pk;
    uint32_t* p_w2pk;
    cudaGetSymbolAddress((void**)&p_h1, g_h1);
    cudaGetSymbolAddress((void**)&p_o1, g_o1);
    cudaGetSymbolAddress((void**)&p_h2, g_h2);
    cudaGetSymbolAddress((void**)&p_o2, g_o2);
    cudaGetSymbolAddress((void**)&p_as1, g_as1);
    cudaGetSymbolAddress((void**)&p_ad1, g_ad1);
    cudaGetSymbolAddress((void**)&p_as2, g_as2);
    cudaGetSymbolAddress((void**)&p_ad2, g_ad2);
    cudaGetSymbolAddress((void**)&p_psum, g_psum);
    cudaGetSymbolAddress((void**)&p_pmax, g_pmax);
    cudaGetSymbolAddress((void**)&p_cnt, g_cnt);
    cudaGetSymbolAddress((void**)&p_deg, g_deg);
    cudaGetSymbolAddress((void**)&p_incl, g_incl);
    cudaGetSymbolAddress((void**)&p_bsum, g_bsum);
    cudaGetSymbolAddress((void**)&p_rowptr, g_rowptr);
    cudaGetSymbolAddress((void**)&p_cursor, g_cursor);
    cudaGetSymbolAddress((void**)&p_adj, g_adj);
    cudaGetSymbolAddress((void**)&p_w1pk, g_w1pk);
    cudaGetSymbolAddress((void**)&p_w2pk, g_w2pk);

    const int TB = 256;
    const int nb = cdiv(n, 1024);

    const int SMEM1 = 1024 + 128 * 576;  // 74752
    const int SMEM2 = 1024 + 64 * 576;   // 37888
    cudaFuncSetAttribute(gemm_mma1, cudaFuncAttributeMaxDynamicSharedMemorySize, SMEM1);
    cudaFuncSetAttribute(gemm_mma2, cudaFuncAttributeMaxDynamicSharedMemorySize, SMEM2);

    static cudaStream_t s2 = nullptr;
    static cudaEvent_t evA = nullptr;
    static cudaEvent_t evB = nullptr;
    if (s2 == nullptr) {
        cudaStreamCreateWithFlags(&s2, cudaStreamNonBlocking);
        cudaEventCreateWithFlags(&evA, cudaEventDisableTiming);
        cudaEventCreateWithFlags(&evB, cudaEventDisableTiming);
    }

    // launch 0: setup (packed weights + deg init + pool fills)
    setup_kernel<<<cdiv(n, TB), TB>>>(W1, W2, p_w1pk, p_w2pk, p_deg, p_psum, p_pmax, p_cnt, n, G);

    // fork CSR chain to side stream
    cudaEventRecord(evA, 0);
    cudaStreamWaitEvent(s2, evA, 0);
    deg_count<<<cdiv(E, TB), TB, 0, s2>>>(ei, p_deg, E);        // launch 1
    scan_block<<<nb, 1024, 0, s2>>>(p_deg, p_incl, p_bsum, n);  // launch 2

    // launch 3 (profiled slot): layer-1 GEMM on main stream
    gemm_mma1<<<cdiv(n, 128), 256, SMEM1>>>(x, p_w1pk, as1, ad1, p_h1, p_as1, p_ad1, n);

    scan_finish<<<cdiv(n, TB), TB, 0, s2>>>(p_incl, p_bsum, p_deg, p_rowptr, p_cursor, n, nb);
    scatter_edges<<<cdiv(E + n, TB), TB, 0, s2>>>(ei, p_cursor, p_adj, E, n);
    cudaEventRecord(evB, s2);

    // join: gat_node1 needs gemm1 + CSR
    cudaStreamWaitEvent(0, evB, 0);
    gat_node1<<<cdiv(n * 32, TB), TB>>>(p_rowptr, p_adj, p_as1, p_ad1, p_h1, b1, p_o1, n);

    // layer 2
    gemm_mma2<<<cdiv(n, 128), 256, SMEM2>>>(p_o1, p_w2pk, as2, ad2, p_h2, p_as2, p_ad2, n);
    gat_node2<<<cdiv(n * 32, TB), TB>>>(p_rowptr, p_adj, p_as2, p_ad2, p_h2, b2, p_o2, n);

    // pooling + head
    pool_seg<<<cdiv(n, 128), 256>>>(p_o2, bat, p_psum, p_pmax, p_cnt, n);
    final_mlp_kernel<<<G, 64>>>(p_psum, p_pmax, p_cnt, Wf1, bf1, Wf2, bf2, out);
}

// round 14
// speedup vs baseline: 1.1124x; 1.0151x over previous
#include <cuda_runtime.h>
#include <cuda_bf16.h>
#include <cuda_fp16.h>
#include <cstdint>
#include <stdint.h>
#include <float.h>
#include <math.h>

#define MAX_NODES 100000
#define MAX_EDGES 600000
#define MAX_GRAPHS 512

// ---------------- scratch (device globals) ----------------
__device__ __half g_h1[(size_t)MAX_NODES * 128];  // layer1 features (fp16, gather-only)
__device__ __half g_o1[(size_t)MAX_NODES * 128];  // layer1 output (fp16: gemm2 input)
__device__ __half g_h2[(size_t)MAX_NODES * 64];   // layer2 features (fp16, gather-only)
__device__ float g_o2[(size_t)MAX_NODES * 64];
__device__ float g_as1[MAX_NODES * 2];
__device__ float g_ad1[MAX_NODES * 2];
__device__ float g_as2[MAX_NODES];
__device__ float g_ad2[MAX_NODES];
// W1: bf16 hi/lo fragment-packed; W2: fp16 hi/lo fragment-packed
__device__ uint32_t g_w1pk[128 * 128];
__device__ uint32_t g_w2pk[64 * 128];
__device__ int g_deg[MAX_NODES];
__device__ int g_incl[MAX_NODES];
__device__ int g_bsum[256];
__device__ int g_rowptr[MAX_NODES + 1];
__device__ int g_cursor[MAX_NODES];
__device__ int g_adj[MAX_EDGES + MAX_NODES];
__device__ float g_psum[MAX_GRAPHS * 64];
__device__ float g_pmax[MAX_GRAPHS * 64];
__device__ float g_cnt[MAX_GRAPHS];

// ---------------- misc ----------------
__device__ __forceinline__ void atomicMaxF(float* addr, float value) {
    if (value >= 0.f) {
        atomicMax((int*)addr, __float_as_int(value));
    } else {
        atomicMin((unsigned int*)addr, __float_as_uint(value));
    }
}

__device__ __forceinline__ void mma_bf16(float* d, const uint32_t* a, uint32_t b0, uint32_t b1) {
    asm volatile(
        "mma.sync.aligned.m16n8k16.row.col.f32.bf16.bf16.f32 "
        "{%0, %1, %2, %3}, {%4, %5, %6, %7}, {%8, %9}, {%0, %1, %2, %3};"
        : "+f"(d[0]), "+f"(d[1]), "+f"(d[2]), "+f"(d[3])
        : "r"(a[0]), "r"(a[1]), "r"(a[2]), "r"(a[3]), "r"(b0), "r"(b1));
}

__device__ __forceinline__ void mma_f16(float* d, const uint32_t* a, uint32_t b0, uint32_t b1) {
    asm volatile(
        "mma.sync.aligned.m16n8k16.row.col.f32.f16.f16.f32 "
        "{%0, %1, %2, %3}, {%4, %5, %6, %7}, {%8, %9}, {%0, %1, %2, %3};"
        : "+f"(d[0]), "+f"(d[1]), "+f"(d[2]), "+f"(d[3])
        : "r"(a[0]), "r"(a[1]), "r"(a[2]), "r"(a[3]), "r"(b0), "r"(b1));
}

__device__ __forceinline__ void cvt_hilo(float2 x, uint32_t& hi, uint32_t& lo) {
    __nv_bfloat16 h0 = __float2bfloat16(x.x);
    __nv_bfloat16 h1 = __float2bfloat16(x.y);
    __nv_bfloat16 l0 = __float2bfloat16(x.x - __bfloat162float(h0));
    __nv_bfloat16 l1 = __float2bfloat16(x.y - __bfloat162float(h1));
    hi = (uint32_t)__bfloat16_as_ushort(h0) | ((uint32_t)__bfloat16_as_ushort(h1) << 16);
    lo = (uint32_t)__bfloat16_as_ushort(l0) | ((uint32_t)__bfloat16_as_ushort(l1) << 16);
}

__device__ __forceinline__ void cvt_hilo_f16(float2 x, uint32_t& hi, uint32_t& lo) {
    __half h0 = __float2half_rn(x.x);
    __half h1 = __float2half_rn(x.y);
    __half l0 = __float2half_rn(x.x - __half2float(h0));
    __half l1 = __float2half_rn(x.y - __half2float(h1));
    hi = (uint32_t)__half_as_ushort(h0) | ((uint32_t)__half_as_ushort(h1) << 16);
    lo = (uint32_t)__half_as_ushort(l0) | ((uint32_t)__half_as_ushort(l1) << 16);
}

// ---------------- setup ----------------
__global__ void setup_kernel(const float* __restrict__ W1, const float* __restrict__ W2,
                             uint32_t* __restrict__ w1pk, uint32_t* __restrict__ w2pk,
                             int* __restrict__ deg, float* __restrict__ psum,
                             float* __restrict__ pmax, float* __restrict__ cnt, int n, int gtot) {
    int idx = blockIdx.x * blockDim.x + threadIdx.x;
    if (idx < n) deg[idx] = 1;
    if (idx < 128 * 64) {
        int nr = idx >> 6;
        int p = idx & 63;
        int k0 = p * 2;
        int ks = k0 >> 4;
        int r = k0 & 15;
        int halfk = r >> 3;
        int j = (r & 7) >> 1;
        float2 v = make_float2(W1[k0 * 128 + nr], W1[(k0 + 1) * 128 + nr]);
        uint32_t hw;
        uint32_t lw;
        cvt_hilo(v, hw, lw);
        int base = ((nr * 8 + ks) * 4 + j) * 4;
        w1pk[base + halfk] = hw;
        w1pk[base + 2 + halfk] = lw;
    }
    if (idx < 64 * 64) {
        int nr = idx >> 6;
        int p = idx & 63;
        int k0 = p * 2;
        int ks = k0 >> 4;
        int r = k0 & 15;
        int halfk = r >> 3;
        int j = (r & 7) >> 1;
        float2 v = make_float2(W2[k0 * 64 + nr], W2[(k0 + 1) * 64 + nr]);
        uint32_t hw;
        uint32_t lw;
        cvt_hilo_f16(v, hw, lw);
        int base = ((nr * 8 + ks) * 4 + j) * 4;
        w2pk[base + halfk] = hw;
        w2pk[base + 2 + halfk] = lw;
    }
    if (idx < gtot * 64) {
        psum[idx] = 0.f;
        pmax[idx] = -FLT_MAX;
    }
    if (idx < gtot) cnt[idx] = 0.f;
}

// ---------------- layer-1 HMMA GEMM: warp = 32 rows x 8 n-tiles (one head) ----------------
__global__ __launch_bounds__(256, 2) void gemm_mma1(
    const float* __restrict__ A, const uint32_t* __restrict__ Wpk,
    const float* __restrict__ avs, const float* __restrict__ avd, __half* __restrict__ Hout,
    float* __restrict__ as_out, float* __restrict__ ad_out, int n) {
    extern __shared__ __align__(16) char sm[];
    constexpr int WST = 576;
    const uint32_t OFF_AVS = 0;
    const uint32_t OFF_AVD = 512;
    const uint32_t OFF_W = 1024;

    const int tid = threadIdx.x;
    const int row0 = blockIdx.x * 128;

    if (tid < 128) {
        reinterpret_cast<float*>(sm + OFF_AVS)[tid] = avs[tid];
        reinterpret_cast<float*>(sm + OFF_AVD)[tid] = avd[tid];
    }
    {
        const uint4* wsrc = reinterpret_cast<const uint4*>(Wpk);
#pragma unroll
        for (int i = tid; i < 128 * 32; i += 256) {
            int nr = i >> 5;
            int w = i & 31;
            *reinterpret_cast<uint4*>(sm + OFF_W + nr * WST + w * 16) = wsrc[i];
        }
    }
    __syncthreads();

    const int warp = tid >> 5;
    const int lane = tid & 31;
    const int g = lane >> 2;
    const int j = lane & 3;
    const int rowgrp = warp >> 1;
    const int colgrp = warp & 1;

    const int r0 = row0 + rowgrp * 32 + g;
    const bool v0 = (r0 < n);
    const bool v1 = (r0 + 8 < n);
    const bool v2 = (r0 + 16 < n);
    const bool v3 = (r0 + 24 < n);
    const float* ap0 = A + (size_t)r0 * 128 + j * 2;
    const float* ap1 = ap0 + 8 * 128;
    const float* ap2 = ap0 + 16 * 128;
    const float* ap3 = ap0 + 24 * 128;

    float acc0[8][4];
    float acc1[8][4];
#pragma unroll
    for (int nt = 0; nt < 8; nt++)
#pragma unroll
        for (int q = 0; q < 4; q++) {
            acc0[nt][q] = 0.f;
            acc1[nt][q] = 0.f;
        }

    const char* bw = sm + OFF_W + (colgrp * 64 + g) * WST + j * 16;
    const float2 z2 = make_float2(0.f, 0.f);
#pragma unroll
    for (int ks = 0; ks < 8; ks++) {
        float2 x00 = v0 ? *reinterpret_cast<const float2*>(ap0 + ks * 16) : z2;
        float2 x01 = v0 ? *reinterpret_cast<const float2*>(ap0 + ks * 16 + 8) : z2;
        float2 x10 = v1 ? *reinterpret_cast<const float2*>(ap1 + ks * 16) : z2;
        float2 x11 = v1 ? *reinterpret_cast<const float2*>(ap1 + ks * 16 + 8) : z2;
        float2 x20 = v2 ? *reinterpret_cast<const float2*>(ap2 + ks * 16) : z2;
        float2 x21 = v2 ? *reinterpret_cast<const float2*>(ap2 + ks * 16 + 8) : z2;
        float2 x30 = v3 ? *reinterpret_cast<const float2*>(ap3 + ks * 16) : z2;
        float2 x31 = v3 ? *reinterpret_cast<const float2*>(ap3 + ks * 16 + 8) : z2;
        uint32_t ahi0[4];
        uint32_t alo0[4];
        uint32_t ahi1[4];
        uint32_t alo1[4];
        cvt_hilo(x00, ahi0[0], alo0[0]);
        cvt_hilo(x10, ahi0[1], alo0[1]);
        cvt_hilo(x01, ahi0[2], alo0[2]);
        cvt_hilo(x11, ahi0[3], alo0[3]);
        cvt_hilo(x20, ahi1[0], alo1[0]);
        cvt_hilo(x30, ahi1[1], alo1[1]);
        cvt_hilo(x21, ahi1[2], alo1[2]);
        cvt_hilo(x31, ahi1[3], alo1[3]);
        const char* bks = bw + ks * 64;
#pragma unroll
        for (int nt = 0; nt < 8; nt++) {
            uint4 b = *reinterpret_cast<const uint4*>(bks + nt * 8 * WST);
            mma_bf16(acc0[nt], ahi0, b.x, b.y);
            mma_bf16(acc0[nt], ahi0, b.z, b.w);
            mma_bf16(acc0[nt], alo0, b.x, b.y);
            mma_bf16(acc1[nt], ahi1, b.x, b.y);
            mma_bf16(acc1[nt], ahi1, b.z, b.w);
            mma_bf16(acc1[nt], alo1, b.x, b.y);
        }
    }

    const float* avs_s = reinterpret_cast<const float*>(sm + OFF_AVS);
    const float* avd_s = reinterpret_cast<const float*>(sm + OFF_AVD);
    float as[4] = {0.f, 0.f, 0.f, 0.f};
    float ds[4] = {0.f, 0.f, 0.f, 0.f};
#pragma unroll
    for (int nt = 0; nt < 8; nt++) {
        int cn = colgrp * 64 + nt * 8 + 2 * j;
        float av0 = avs_s[cn];
        float av1 = avs_s[cn + 1];
        float dv0 = avd_s[cn];
        float dv1 = avd_s[cn + 1];
        as[0] += acc0[nt][0] * av0 + acc0[nt][1] * av1;
        as[1] += acc0[nt][2] * av0 + acc0[nt][3] * av1;
        as[2] += acc1[nt][0] * av0 + acc1[nt][1] * av1;
        as[3] += acc1[nt][2] * av0 + acc1[nt][3] * av1;
        ds[0] += acc0[nt][0] * dv0 + acc0[nt][1] * dv1;
        ds[1] += acc0[nt][2] * dv0 + acc0[nt][3] * dv1;
        ds[2] += acc1[nt][0] * dv0 + acc1[nt][1] * dv1;
        ds[3] += acc1[nt][2] * dv0 + acc1[nt][3] * dv1;
        if (v0)
            *reinterpret_cast<__half2*>(Hout + (size_t)r0 * 128 + cn) =
                __floats2half2_rn(acc0[nt][0], acc0[nt][1]);
        if (v1)
            *reinterpret_cast<__half2*>(Hout + (size_t)(r0 + 8) * 128 + cn) =
                __floats2half2_rn(acc0[nt][2], acc0[nt][3]);
        if (v2)
            *reinterpret_cast<__half2*>(Hout + (size_t)(r0 + 16) * 128 + cn) =
                __floats2half2_rn(acc1[nt][0], acc1[nt][1]);
        if (v3)
            *reinterpret_cast<__half2*>(Hout + (size_t)(r0 + 24) * 128 + cn) =
                __floats2half2_rn(acc1[nt][2], acc1[nt][3]);
    }
#pragma unroll
    for (int off = 1; off <= 2; off <<= 1) {
#pragma unroll
        for (int q = 0; q < 4; q++) {
            as[q] += __shfl_xor_sync(0xffffffffu, as[q], off);
            ds[q] += __shfl_xor_sync(0xffffffffu, ds[q], off);
        }
    }
    if (j == 0) {
        const bool vr[4] = {v0, v1, v2, v3};
#pragma unroll
        for (int q = 0; q < 4; q++) {
            if (vr[q]) {
                int r = r0 + q * 8;
                as_out[(size_t)r * 2 + colgrp] = as[q];
                ad_out[(size_t)r * 2 + colgrp] = ds[q];
            }
        }
    }
}

// ---------------- layer-2 HMMA GEMM: fp16 A (exact) x fp16 W hi/lo (2 MMAs) ----------------
__global__ __launch_bounds__(256, 3) void gemm_mma2(
    const __half* __restrict__ A, const uint32_t* __restrict__ Wpk,
    const float* __restrict__ avs, const float* __restrict__ avd, __half* __restrict__ Hout,
    float* __restrict__ as_out, float* __restrict__ ad_out, int n) {
    extern __shared__ __align__(16) char sm[];
    constexpr int NOUT = 64;
    constexpr int NT = 8;
    constexpr int WST = 576;
    const uint32_t OFF_AVS = 0;
    const uint32_t OFF_AVD = 256;
    const uint32_t OFF_W = 512;

    const int tid = threadIdx.x;
    const int row0 = blockIdx.x * 128;

    if (tid < NOUT) {
        reinterpret_cast<float*>(sm + OFF_AVS)[tid] = avs[tid];
        reinterpret_cast<float*>(sm + OFF_AVD)[tid] = avd[tid];
    }
    {
        const uint4* wsrc = reinterpret_cast<const uint4*>(Wpk);
#pragma unroll
        for (int i = tid; i < NOUT * 32; i += 256) {
            int nr = i >> 5;
            int w = i & 31;
            *reinterpret_cast<uint4*>(sm + OFF_W + nr * WST + w * 16) = wsrc[i];
        }
    }
    __syncthreads();

    const int warp = tid >> 5;
    const int lane = tid & 31;
    const int g = lane >> 2;
    const int j = lane & 3;
    const int wm0 = warp * 16;

    const int rowA0 = row0 + wm0 + g;
    const int rowA1 = rowA0 + 8;
    const bool v0r = rowA0 < n;
    const bool v1r = rowA1 < n;
    const __half* a0p = A + (size_t)rowA0 * 128 + j * 2;
    const __half* a1p = A + (size_t)rowA1 * 128 + j * 2;

    float acc[NT][4];
#pragma unroll
    for (int nt = 0; nt < NT; nt++)
#pragma unroll
        for (int q = 0; q < 4; q++) acc[nt][q] = 0.f;

    const char* bw = sm + OFF_W + g * WST + j * 16;
#pragma unroll
    for (int ks = 0; ks < 8; ks++) {
        uint32_t a[4];
        a[0] = v0r ? *reinterpret_cast<const uint32_t*>(a0p + ks * 16) : 0u;
        a[1] = v1r ? *reinterpret_cast<const uint32_t*>(a1p + ks * 16) : 0u;
        a[2] = v0r ? *reinterpret_cast<const uint32_t*>(a0p + ks * 16 + 8) : 0u;
        a[3] = v1r ? *reinterpret_cast<const uint32_t*>(a1p + ks * 16 + 8) : 0u;
        const char* bks = bw + ks * 64;
#pragma unroll
        for (int nt = 0; nt < NT; nt++) {
            uint4 b = *reinterpret_cast<const uint4*>(bks + nt * 8 * WST);
            mma_f16(acc[nt], a, b.x, b.y);   // A * W_hi
            mma_f16(acc[nt], a, b.z, b.w);   // A * W_lo
        }
    }

    const float* avs_s = reinterpret_cast<const float*>(sm + OFF_AVS);
    const float* avd_s = reinterpret_cast<const float*>(sm + OFF_AVD);
    float asum[2] = {0.f, 0.f};
    float dsum[2] = {0.f, 0.f};
#pragma unroll
    for (int nt = 0; nt < NT; nt++) {
        int cn = nt * 8 + 2 * j;
        float av0 = avs_s[cn];
        float av1 = avs_s[cn + 1];
        float dv0 = avd_s[cn];
        float dv1 = avd_s[cn + 1];
        asum[0] += acc[nt][0] * av0 + acc[nt][1] * av1;
        asum[1] += acc[nt][2] * av0 + acc[nt][3] * av1;
        dsum[0] += acc[nt][0] * dv0 + acc[nt][1] * dv1;
        dsum[1] += acc[nt][2] * dv0 + acc[nt][3] * dv1;
        if (v0r)
            *reinterpret_cast<__half2*>(Hout + (size_t)rowA0 * NOUT + cn) =
                __floats2half2_rn(acc[nt][0], acc[nt][1]);
        if (v1r)
            *reinterpret_cast<__half2*>(Hout + (size_t)rowA1 * NOUT + cn) =
                __floats2half2_rn(acc[nt][2], acc[nt][3]);
    }
#pragma unroll
    for (int off = 1; off <= 2; off <<= 1) {
        asum[0] += __shfl_xor_sync(0xffffffffu, asum[0], off);
        asum[1] += __shfl_xor_sync(0xffffffffu, asum[1], off);
        dsum[0] += __shfl_xor_sync(0xffffffffu, dsum[0], off);
        dsum[1] += __shfl_xor_sync(0xffffffffu, dsum[1], off);
    }
    if (j == 0) {
        if (v0r) {
            as_out[rowA0] = asum[0];
            ad_out[rowA0] = dsum[0];
        }
        if (v1r) {
            as_out[rowA1] = asum[1];
            ad_out[rowA1] = dsum[1];
        }
    }
}

// ---------------- CSR build ----------------
__global__ void deg_count(const int* __restrict__ ei, int* __restrict__ deg, int E) {
    int i = blockIdx.x * blockDim.x + threadIdx.x;
    if (i < E) atomicAdd(&deg[ei[E + i]], 1);
}

__global__ void scan_block(const int* __restrict__ deg, int* __restrict__ incl,
                           int* __restrict__ bsum, int n) {
    __shared__ int wsum[32];
    int tid = threadIdx.x;
    int lane = tid & 31;
    int wid = tid >> 5;
    int gid = blockIdx.x * 1024 + tid;
    int v = (gid < n) ? deg[gid] : 0;
#pragma unroll
    for (int off = 1; off < 32; off <<= 1) {
        int t = __shfl_up_sync(0xffffffffu, v, off);
        if (lane >= off) v += t;
    }
    if (lane == 31) wsum[wid] = v;
    __syncthreads();
    if (wid == 0) {
        int w = wsum[lane];
#pragma unroll
        for (int off = 1; off < 32; off <<= 1) {
            int t = __shfl_up_sync(0xffffffffu, w, off);
            if (lane >= off) w += t;
        }
        wsum[lane] = w;
    }
    __syncthreads();
    if (wid > 0) v += wsum[wid - 1];
    if (gid < n) incl[gid] = v;
    if (tid == 1023) bsum[blockIdx.x] = v;
}

__global__ void scan_finish(const int* __restrict__ incl, const int* __restrict__ bsum,
                            const int* __restrict__ deg, int* __restrict__ rowptr,
                            int* __restrict__ cursor, int n, int nb) {
    __shared__ int pre[128];
    int tid = threadIdx.x;
    if (tid < 32) {
        int base = tid * 4;
        int v[4];
#pragma unroll
        for (int q = 0; q < 4; q++) v[q] = (base + q < nb) ? bsum[base + q] : 0;
        int tot = v[0] + v[1] + v[2] + v[3];
        int inc = tot;
#pragma unroll
        for (int off = 1; off < 32; off <<= 1) {
            int t = __shfl_up_sync(0xffffffffu, inc, off);
            if (tid >= off) inc += t;
        }
        int run = inc - tot;
#pragma unroll
        for (int q = 0; q < 4; q++) {
            pre[base + q] = run;
            run += v[q];
        }
    }
    __syncthreads();
    int i = blockIdx.x * blockDim.x + tid;
    if (i < n) {
        int end = incl[i] + pre[i >> 10];
        rowptr[i + 1] = end;
        cursor[i] = end - deg[i];
    }
    if (i == 0) rowptr[0] = 0;
}

__global__ void scatter_edges(const int* __restrict__ ei, int* __restrict__ cursor,
                              int* __restrict__ adj, int E, int n) {
    int i = blockIdx.x * blockDim.x + threadIdx.x;
    if (i >= E + n) return;
    int s;
    int d;
    if (i < E) {
        s = ei[i];
        d = ei[E + i];
    } else {
        s = i - E;
        d = s;
    }
    int pos = atomicAdd(&cursor[d], 1);
    adj[pos] = s;
}

// ---------------- layer1 node aggregation (fp16 gather, fp16 out) ----------------
__global__ void gat_node1(const int* __restrict__ rowptr, const int* __restrict__ adj,
                          const float* __restrict__ as, const float* __restrict__ ad,
                          const __half* __restrict__ h, const float* __restrict__ b,
                          __half* __restrict__ out, int n) {
    int node = (blockIdx.x * blockDim.x + threadIdx.x) >> 5;
    int lane = threadIdx.x & 31;
    if (node >= n) return;
    int start = rowptr[node];
    int end = rowptr[node + 1];
    float ad0 = ad[node * 2];
    float ad1 = ad[node * 2 + 1];
    bool hi = lane >= 16;

    float4 acc = make_float4(0.f, 0.f, 0.f, 0.f);
    float den0 = 0.f;
    float den1 = 0.f;
    for (int base = start; base < end; base += 32) {
        int cnt = min(32, end - base);
        int s_l = 0;
        float ex0_l = 0.f;
        float ex1_l = 0.f;
        if (lane < cnt) {
            s_l = adj[base + lane];
            float e0 = as[s_l * 2] + ad0;
            e0 = e0 >= 0.f ? e0 : 0.2f * e0;
            float e1 = as[s_l * 2 + 1] + ad1;
            e1 = e1 >= 0.f ? e1 : 0.2f * e1;
            ex0_l = expf(e0);
            ex1_l = expf(e1);
        }
        den0 += ex0_l;
        den1 += ex1_l;
#pragma unroll 4
        for (int tt = 0; tt < cnt; tt++) {
            int s = __shfl_sync(0xffffffffu, s_l, tt);
            float ex0 = __shfl_sync(0xffffffffu, ex0_l, tt);
            float ex1 = __shfl_sync(0xffffffffu, ex1_l, tt);
            float ex = hi ? ex1 : ex0;
            uint2 u = reinterpret_cast<const uint2*>(h + (size_t)s * 128)[lane];
            __half2 p0 = *reinterpret_cast<const __half2*>(&u.x);
            __half2 p1 = *reinterpret_cast<const __half2*>(&u.y);
            float2 f0 = __half22float2(p0);
            float2 f1 = __half22float2(p1);
            acc.x = fmaf(ex, f0.x, acc.x);
            acc.y = fmaf(ex, f0.y, acc.y);
            acc.z = fmaf(ex, f1.x, acc.z);
            acc.w = fmaf(ex, f1.y, acc.w);
        }
    }
    for (int o = 16; o > 0; o >>= 1) {
        den0 += __shfl_xor_sync(0xffffffffu, den0, o);
        den1 += __shfl_xor_sync(0xffffffffu, den1, o);
    }
    float den = fmaxf(hi ? den1 : den0, 1e-16f);
    float inv = 1.f / den;
    float4 bb = reinterpret_cast<const float4*>(b)[lane];
    __half2 o0 = __floats2half2_rn(fmaxf(fmaf(acc.x, inv, bb.x), 0.f),
                                   fmaxf(fmaf(acc.y, inv, bb.y), 0.f));
    __half2 o1v = __floats2half2_rn(fmaxf(fmaf(acc.z, inv, bb.z), 0.f),
                                    fmaxf(fmaf(acc.w, inv, bb.w), 0.f));
    uint2 u;
    u.x = *reinterpret_cast<uint32_t*>(&o0);
    u.y = *reinterpret_cast<uint32_t*>(&o1v);
    reinterpret_cast<uint2*>(out + (size_t)node * 128)[lane] = u;
}

// ---------------- layer2 node aggregation (fp16 gather) ----------------
__global__ void gat_node2(const int* __restrict__ rowptr, const int* __restrict__ adj,
                          const float* __restrict__ as, const float* __restrict__ ad,
                          const __half* __restrict__ h, const float* __restrict__ b,
                          float* __restrict__ out, int n) {
    int node = (blockIdx.x * blockDim.x + threadIdx.x) >> 5;
    int lane = threadIdx.x & 31;
    if (node >= n) return;
    int start = rowptr[node];
    int end = rowptr[node + 1];
    float add = ad[node];

    float2 acc = make_float2(0.f, 0.f);
    float den = 0.f;
    for (int base = start; base < end; base += 32) {
        int cnt = min(32, end - base);
        int s_l = 0;
        float ex_l = 0.f;
        if (lane < cnt) {
            s_l = adj[base + lane];
            float e = as[s_l] + add;
            e = e >= 0.f ? e : 0.2f * e;
            ex_l = expf(e);
        }
        den += ex_l;
#pragma unroll 4
        for (int tt = 0; tt < cnt; tt++) {
            int s = __shfl_sync(0xffffffffu, s_l, tt);
            float ex = __shfl_sync(0xffffffffu, ex_l, tt);
            __half2 p = reinterpret_cast<const __half2*>(h + (size_t)s * 64)[lane];
            float2 f = __half22float2(p);
            acc.x = fmaf(ex, f.x, acc.x);
            acc.y = fmaf(ex, f.y, acc.y);
        }
    }
    for (int o = 16; o > 0; o >>= 1) {
        den += __shfl_xor_sync(0xffffffffu, den, o);
    }
    float inv = 1.f / fmaxf(den, 1e-16f);
    float2 bb = reinterpret_cast<const float2*>(b)[lane];
    float2 o;
    o.x = fmaf(acc.x, inv, bb.x);
    o.y = fmaf(acc.y, inv, bb.y);
    reinterpret_cast<float2*>(out + (size_t)node * 64)[lane] = o;
}

// ---------------- per-graph pooling (batch sorted) ----------------
__global__ void pool_seg(const float* __restrict__ h, const int* __restrict__ batch,
                         float* __restrict__ psum, float* __restrict__ pmax,
                         float* __restrict__ cnt, int n) {
    int n0 = blockIdx.x * 128;
    int t = threadIdx.x;
    int c = t & 63;
    int off = t >> 6;
    int gcur = -1;
    float sum = 0.f;
    float mx = -FLT_MAX;
    float count = 0.f;
    int lim = min(n0 + 128, n);
    for (int i = n0 + off; i < lim; i += 4) {
        int g = batch[i];
        if (g != gcur) {
            if (gcur >= 0) {
                atomicAdd(&psum[gcur * 64 + c], sum);
                atomicMaxF(&pmax[gcur * 64 + c], mx);
                if (c == 0) atomicAdd(&cnt[gcur], count);
            }
            gcur = g;
            sum = 0.f;
            mx = -FLT_MAX;
            count = 0.f;
        }
        float v = h[(size_t)i * 64 + c];
        sum += v;
        mx = fmaxf(mx, v);
        count += 1.f;
    }
    if (gcur >= 0) {
        atomicAdd(&psum[gcur * 64 + c], sum);
        atomicMaxF(&pmax[gcur * 64 + c], mx);
        if (c == 0) atomicAdd(&cnt[gcur], count);
    }
}

// ---------------- final MLP head ----------------
__global__ void final_mlp_kernel(const float* __restrict__ psum, const float* __restrict__ pmax,
                                 const float* __restrict__ cnt, const float* __restrict__ Wf1,
                                 const float* __restrict__ bf1, const float* __restrict__ Wf2,
                                 const float* __restrict__ bf2, float* __restrict__ out) {
    __shared__ float pooled[128];
    __shared__ float red[64];
    int g = blockIdx.x;
    int t = threadIdx.x;
    float c = cnt[g];
    pooled[t] = psum[g * 64 + t] / fmaxf(c, 1.f);
    pooled[64 + t] = (c > 0.f) ? pmax[g * 64 + t] : 0.f;
    __syncthreads();
    float hj = bf1[t];
    for (int k = 0; k < 128; k++) {
        hj = fmaf(pooled[k], Wf1[k * 64 + t], hj);
    }
    hj = fmaxf(hj, 0.f);
    red[t] = hj * Wf2[t];
    __syncthreads();
    for (int s = 32; s > 0; s >>= 1) {
        if (t < s) red[t] += red[t + s];
        __syncthreads();
    }
    if (t == 0) out[g] = red[0] + bf2[0];
}

// ---------------- host launch ----------------
static inline int cdiv(int a, int b) { return (a + b - 1) / b; }

extern "C" void kernel_launch(void* const* d_in, const int* in_sizes, int n_in,
                              void* d_out, int out_size) {
    const float* x = (const float*)d_in[0];
    const int* ei = (const int*)d_in[1];
    const int* bat = (const int*)d_in[2];
    const float* W1 = (const float*)d_in[3];
    const float* as1 = (const float*)d_in[4];
    const float* ad1 = (const float*)d_in[5];
    const float* b1 = (const float*)d_in[6];
    const float* W2 = (const float*)d_in[7];
    const float* as2 = (const float*)d_in[8];
    const float* ad2 = (const float*)d_in[9];
    const float* b2 = (const float*)d_in[10];
    const float* Wf1 = (const float*)d_in[11];
    const float* bf1 = (const float*)d_in[12];
    const float* Wf2 = (const float*)d_in[13];
    const float* bf2 = (const float*)d_in[14];
    float* out = (float*)d_out;

    const int n = in_sizes[0] / 128;
    const int E = in_sizes[1] / 2;
    const int G = out_size;

    __half* p_h1;
    __half* p_o1;
    __half* p_h2;
    float* p_o2;
    float* p_as1;
    float* p_ad1;
    float* p_as2;
    float* p_ad2;
    float* p_psum;
    float* p_pmax;
    float* p_cnt;
    int* p_deg;
    int* p_incl;
    int* p_bsum;
    int* p_rowptr;
    int* p_cursor;
    int* p_adj;
    uint32_t* p_w1pk;
    uint32_t* p_w2pk;
    cudaGetSymbolAddress((void**)&p_h1, g_h1);
    cudaGetSymbolAddress((void**)&p_o1, g_o1);
    cudaGetSymbolAddress((void**)&p_h2, g_h2);
    cudaGetSymbolAddress((void**)&p_o2, g_o2);
    cudaGetSymbolAddress((void**)&p_as1, g_as1);
    cudaGetSymbolAddress((void**)&p_ad1, g_ad1);
    cudaGetSymbolAddress((void**)&p_as2, g_as2);
    cudaGetSymbolAddress((void**)&p_ad2, g_ad2);
    cudaGetSymbolAddress((void**)&p_psum, g_psum);
    cudaGetSymbolAddress((void**)&p_pmax, g_pmax);
    cudaGetSymbolAddress((void**)&p_cnt, g_cnt);
    cudaGetSymbolAddress((void**)&p_deg, g_deg);
    cudaGetSymbolAddress((void**)&p_incl, g_incl);
    cudaGetSymbolAddress((void**)&p_bsum, g_bsum);
    cudaGetSymbolAddress((void**)&p_rowptr, g_rowptr);
    cudaGetSymbolAddress((void**)&p_cursor, g_cursor);
    cudaGetSymbolAddress((void**)&p_adj, g_adj);
    cudaGetSymbolAddress((void**)&p_w1pk, g_w1pk);
    cudaGetSymbolAddress((void**)&p_w2pk, g_w2pk);

    const int TB = 256;
    const int nb = cdiv(n, 1024);

    const int SMEM1 = 1024 + 128 * 576;  // 74752
    const int SMEM2 = 512 + 64 * 576;    // 37376
    cudaFuncSetAttribute(gemm_mma1, cudaFuncAttributeMaxDynamicSharedMemorySize, SMEM1);
    cudaFuncSetAttribute(gemm_mma2, cudaFuncAttributeMaxDynamicSharedMemorySize, SMEM2);

    static cudaStream_t s2 = nullptr;
    static cudaEvent_t evA = nullptr;
    static cudaEvent_t evB = nullptr;
    if (s2 == nullptr) {
        cudaStreamCreateWithFlags(&s2, cudaStreamNonBlocking);
        cudaEventCreateWithFlags(&evA, cudaEventDisableTiming);
        cudaEventCreateWithFlags(&evB, cudaEventDisableTiming);
    }

    // launch 0: setup (packed weights + deg init + pool fills)
    setup_kernel<<<cdiv(n, TB), TB>>>(W1, W2, p_w1pk, p_w2pk, p_deg, p_psum, p_pmax, p_cnt, n, G);

    // fork CSR chain to side stream
    cudaEventRecord(evA, 0);
    cudaStreamWaitEvent(s2, evA, 0);
    deg_count<<<cdiv(E, TB), TB, 0, s2>>>(ei, p_deg, E);        // launch 1
    scan_block<<<nb, 1024, 0, s2>>>(p_deg, p_incl, p_bsum, n);  // launch 2

    // launch 3 (profiled slot): layer-1 GEMM on main stream
    gemm_mma1<<<cdiv(n, 128), 256, SMEM1>>>(x, p_w1pk, as1, ad1, p_h1, p_as1, p_ad1, n);

    scan_finish<<<cdiv(n, TB), TB, 0, s2>>>(p_incl, p_bsum, p_deg, p_rowptr, p_cursor, n, nb);
    scatter_edges<<<cdiv(E + n, TB), TB, 0, s2>>>(ei, p_cursor, p_adj, E, n);
    cudaEventRecord(evB, s2);

    // join: gat_node1 needs gemm1 + CSR
    cudaStreamWaitEvent(0, evB, 0);
    gat_node1<<<cdiv(n * 32, TB), TB>>>(p_rowptr, p_adj, p_as1, p_ad1, p_h1, b1, p_o1, n);

    // layer 2
    gemm_mma2<<<cdiv(n, 128), 256, SMEM2>>>(p_o1, p_w2pk, as2, ad2, p_h2, p_as2, p_ad2, n);
    gat_node2<<<cdiv(n * 32, TB), TB>>>(p_rowptr, p_adj, p_as2, p_ad2, p_h2, b2, p_o2, n);

    // pooling + head
    pool_seg<<<cdiv(n, 128), 256>>>(p_o2, bat, p_psum, p_pmax, p_cnt, n);
    final_mlp_kernel<<<G, 64>>>(p_psum, p_pmax, p_cnt, Wf1, bf1, Wf2, bf2, out);
}

// round 15
// speedup vs baseline: 1.1442x; 1.0286x over previous
#include <cuda_runtime.h>
#include <cuda_bf16.h>
#include <cuda_fp16.h>
#include <cstdint>
#include <stdint.h>
#include <float.h>
#include <math.h>

#define MAX_NODES 100000
#define MAX_EDGES 600000
#define MAX_GRAPHS 512

// ---------------- scratch (device globals) ----------------
__device__ __half g_h1[(size_t)MAX_NODES * 128];  // layer1 features (fp16, gather-only)
__device__ __half g_o1[(size_t)MAX_NODES * 128];  // layer1 output (fp16: gemm2 input)
__device__ __half g_h2[(size_t)MAX_NODES * 64];   // layer2 features (fp16, gather-only)
__device__ float g_o2[(size_t)MAX_NODES * 64];
__device__ float g_as1[MAX_NODES * 2];
__device__ float g_ad1[MAX_NODES * 2];
__device__ float g_as2[MAX_NODES];
__device__ float g_ad2[MAX_NODES];
// W1/W2: fp16 hi/lo fragment-packed: word idx = ((n*8+ks)*4+j)*4 + {hi_k, hi_k8, lo_k, lo_k8}
__device__ uint32_t g_w1pk[128 * 128];
__device__ uint32_t g_w2pk[64 * 128];
__device__ int g_deg[MAX_NODES];
__device__ int g_incl[MAX_NODES];
__device__ int g_bsum[256];
__device__ int g_rowptr[MAX_NODES + 1];
__device__ int g_cursor[MAX_NODES];
__device__ int g_adj[MAX_EDGES + MAX_NODES];
__device__ float g_psum[MAX_GRAPHS * 64];
__device__ float g_pmax[MAX_GRAPHS * 64];
__device__ float g_cnt[MAX_GRAPHS];

// ---------------- misc ----------------
__device__ __forceinline__ void atomicMaxF(float* addr, float value) {
    if (value >= 0.f) {
        atomicMax((int*)addr, __float_as_int(value));
    } else {
        atomicMin((unsigned int*)addr, __float_as_uint(value));
    }
}

__device__ __forceinline__ void mma_f16(float* d, const uint32_t* a, uint32_t b0, uint32_t b1) {
    asm volatile(
        "mma.sync.aligned.m16n8k16.row.col.f32.f16.f16.f32 "
        "{%0, %1, %2, %3}, {%4, %5, %6, %7}, {%8, %9}, {%0, %1, %2, %3};"
        : "+f"(d[0]), "+f"(d[1]), "+f"(d[2]), "+f"(d[3])
        : "r"(a[0]), "r"(a[1]), "r"(a[2]), "r"(a[3]), "r"(b0), "r"(b1));
}

__device__ __forceinline__ uint32_t pack_f16(float2 x) {
    __half2 h = __floats2half2_rn(x.x, x.y);
    return *reinterpret_cast<uint32_t*>(&h);
}

__device__ __forceinline__ void cvt_hilo_f16(float2 x, uint32_t& hi, uint32_t& lo) {
    __half h0 = __float2half_rn(x.x);
    __half h1 = __float2half_rn(x.y);
    __half l0 = __float2half_rn(x.x - __half2float(h0));
    __half l1 = __float2half_rn(x.y - __half2float(h1));
    hi = (uint32_t)__half_as_ushort(h0) | ((uint32_t)__half_as_ushort(h1) << 16);
    lo = (uint32_t)__half_as_ushort(l0) | ((uint32_t)__half_as_ushort(l1) << 16);
}

// ---------------- setup ----------------
__global__ void setup_kernel(const float* __restrict__ W1, const float* __restrict__ W2,
                             uint32_t* __restrict__ w1pk, uint32_t* __restrict__ w2pk,
                             int* __restrict__ deg, float* __restrict__ psum,
                             float* __restrict__ pmax, float* __restrict__ cnt, int n, int gtot) {
    int idx = blockIdx.x * blockDim.x + threadIdx.x;
    if (idx < n) deg[idx] = 1;
    if (idx < 128 * 64) {
        int nr = idx >> 6;
        int p = idx & 63;
        int k0 = p * 2;
        int ks = k0 >> 4;
        int r = k0 & 15;
        int halfk = r >> 3;
        int j = (r & 7) >> 1;
        float2 v = make_float2(W1[k0 * 128 + nr], W1[(k0 + 1) * 128 + nr]);
        uint32_t hw;
        uint32_t lw;
        cvt_hilo_f16(v, hw, lw);
        int base = ((nr * 8 + ks) * 4 + j) * 4;
        w1pk[base + halfk] = hw;
        w1pk[base + 2 + halfk] = lw;
    }
    if (idx < 64 * 64) {
        int nr = idx >> 6;
        int p = idx & 63;
        int k0 = p * 2;
        int ks = k0 >> 4;
        int r = k0 & 15;
        int halfk = r >> 3;
        int j = (r & 7) >> 1;
        float2 v = make_float2(W2[k0 * 64 + nr], W2[(k0 + 1) * 64 + nr]);
        uint32_t hw;
        uint32_t lw;
        cvt_hilo_f16(v, hw, lw);
        int base = ((nr * 8 + ks) * 4 + j) * 4;
        w2pk[base + halfk] = hw;
        w2pk[base + 2 + halfk] = lw;
    }
    if (idx < gtot * 64) {
        psum[idx] = 0.f;
        pmax[idx] = -FLT_MAX;
    }
    if (idx < gtot) cnt[idx] = 0.f;
}

// ---------------- layer-1 HMMA GEMM: fp16 A x fp16 W hi/lo (2 MMAs per frag) ----------------
// warp = 32 rows x 8 n-tiles (one head); 8 warps = 4 rowgrps x 2 colgrps
__global__ __launch_bounds__(256, 2) void gemm_mma1(
    const float* __restrict__ A, const uint32_t* __restrict__ Wpk,
    const float* __restrict__ avs, const float* __restrict__ avd, __half* __restrict__ Hout,
    float* __restrict__ as_out, float* __restrict__ ad_out, int n) {
    extern __shared__ __align__(16) char sm[];
    constexpr int WST = 576;
    const uint32_t OFF_AVS = 0;
    const uint32_t OFF_AVD = 512;
    const uint32_t OFF_W = 1024;

    const int tid = threadIdx.x;
    const int row0 = blockIdx.x * 128;

    if (tid < 128) {
        reinterpret_cast<float*>(sm + OFF_AVS)[tid] = avs[tid];
        reinterpret_cast<float*>(sm + OFF_AVD)[tid] = avd[tid];
    }
    {
        const uint4* wsrc = reinterpret_cast<const uint4*>(Wpk);
#pragma unroll
        for (int i = tid; i < 128 * 32; i += 256) {
            int nr = i >> 5;
            int w = i & 31;
            *reinterpret_cast<uint4*>(sm + OFF_W + nr * WST + w * 16) = wsrc[i];
        }
    }
    __syncthreads();

    const int warp = tid >> 5;
    const int lane = tid & 31;
    const int g = lane >> 2;
    const int j = lane & 3;
    const int rowgrp = warp >> 1;
    const int colgrp = warp & 1;

    const int r0 = row0 + rowgrp * 32 + g;
    const bool v0 = (r0 < n);
    const bool v1 = (r0 + 8 < n);
    const bool v2 = (r0 + 16 < n);
    const bool v3 = (r0 + 24 < n);
    const float* ap0 = A + (size_t)r0 * 128 + j * 2;
    const float* ap1 = ap0 + 8 * 128;
    const float* ap2 = ap0 + 16 * 128;
    const float* ap3 = ap0 + 24 * 128;

    float acc0[8][4];
    float acc1[8][4];
#pragma unroll
    for (int nt = 0; nt < 8; nt++)
#pragma unroll
        for (int q = 0; q < 4; q++) {
            acc0[nt][q] = 0.f;
            acc1[nt][q] = 0.f;
        }

    const char* bw = sm + OFF_W + (colgrp * 64 + g) * WST + j * 16;
    const float2 z2 = make_float2(0.f, 0.f);
#pragma unroll
    for (int ks = 0; ks < 8; ks++) {
        float2 x00 = v0 ? *reinterpret_cast<const float2*>(ap0 + ks * 16) : z2;
        float2 x01 = v0 ? *reinterpret_cast<const float2*>(ap0 + ks * 16 + 8) : z2;
        float2 x10 = v1 ? *reinterpret_cast<const float2*>(ap1 + ks * 16) : z2;
        float2 x11 = v1 ? *reinterpret_cast<const float2*>(ap1 + ks * 16 + 8) : z2;
        float2 x20 = v2 ? *reinterpret_cast<const float2*>(ap2 + ks * 16) : z2;
        float2 x21 = v2 ? *reinterpret_cast<const float2*>(ap2 + ks * 16 + 8) : z2;
        float2 x30 = v3 ? *reinterpret_cast<const float2*>(ap3 + ks * 16) : z2;
        float2 x31 = v3 ? *reinterpret_cast<const float2*>(ap3 + ks * 16 + 8) : z2;
        uint32_t a0[4];
        uint32_t a1[4];
        a0[0] = pack_f16(x00);
        a0[1] = pack_f16(x10);
        a0[2] = pack_f16(x01);
        a0[3] = pack_f16(x11);
        a1[0] = pack_f16(x20);
        a1[1] = pack_f16(x30);
        a1[2] = pack_f16(x21);
        a1[3] = pack_f16(x31);
        const char* bks = bw + ks * 64;
#pragma unroll
        for (int nt = 0; nt < 8; nt++) {
            uint4 b = *reinterpret_cast<const uint4*>(bks + nt * 8 * WST);
            mma_f16(acc0[nt], a0, b.x, b.y);
            mma_f16(acc0[nt], a0, b.z, b.w);
            mma_f16(acc1[nt], a1, b.x, b.y);
            mma_f16(acc1[nt], a1, b.z, b.w);
        }
    }

    const float* avs_s = reinterpret_cast<const float*>(sm + OFF_AVS);
    const float* avd_s = reinterpret_cast<const float*>(sm + OFF_AVD);
    float as[4] = {0.f, 0.f, 0.f, 0.f};
    float ds[4] = {0.f, 0.f, 0.f, 0.f};
#pragma unroll
    for (int nt = 0; nt < 8; nt++) {
        int cn = colgrp * 64 + nt * 8 + 2 * j;
        float av0 = avs_s[cn];
        float av1 = avs_s[cn + 1];
        float dv0 = avd_s[cn];
        float dv1 = avd_s[cn + 1];
        as[0] += acc0[nt][0] * av0 + acc0[nt][1] * av1;
        as[1] += acc0[nt][2] * av0 + acc0[nt][3] * av1;
        as[2] += acc1[nt][0] * av0 + acc1[nt][1] * av1;
        as[3] += acc1[nt][2] * av0 + acc1[nt][3] * av1;
        ds[0] += acc0[nt][0] * dv0 + acc0[nt][1] * dv1;
        ds[1] += acc0[nt][2] * dv0 + acc0[nt][3] * dv1;
        ds[2] += acc1[nt][0] * dv0 + acc1[nt][1] * dv1;
        ds[3] += acc1[nt][2] * dv0 + acc1[nt][3] * dv1;
        if (v0)
            *reinterpret_cast<__half2*>(Hout + (size_t)r0 * 128 + cn) =
                __floats2half2_rn(acc0[nt][0], acc0[nt][1]);
        if (v1)
            *reinterpret_cast<__half2*>(Hout + (size_t)(r0 + 8) * 128 + cn) =
                __floats2half2_rn(acc0[nt][2], acc0[nt][3]);
        if (v2)
            *reinterpret_cast<__half2*>(Hout + (size_t)(r0 + 16) * 128 + cn) =
                __floats2half2_rn(acc1[nt][0], acc1[nt][1]);
        if (v3)
            *reinterpret_cast<__half2*>(Hout + (size_t)(r0 + 24) * 128 + cn) =
                __floats2half2_rn(acc1[nt][2], acc1[nt][3]);
    }
#pragma unroll
    for (int off = 1; off <= 2; off <<= 1) {
#pragma unroll
        for (int q = 0; q < 4; q++) {
            as[q] += __shfl_xor_sync(0xffffffffu, as[q], off);
            ds[q] += __shfl_xor_sync(0xffffffffu, ds[q], off);
        }
    }
    if (j == 0) {
        const bool vr[4] = {v0, v1, v2, v3};
#pragma unroll
        for (int q = 0; q < 4; q++) {
            if (vr[q]) {
                int r = r0 + q * 8;
                as_out[(size_t)r * 2 + colgrp] = as[q];
                ad_out[(size_t)r * 2 + colgrp] = ds[q];
            }
        }
    }
}

// ---------------- layer-2 HMMA GEMM: fp16 A (exact) x fp16 W hi/lo ----------------
__global__ __launch_bounds__(256, 3) void gemm_mma2(
    const __half* __restrict__ A, const uint32_t* __restrict__ Wpk,
    const float* __restrict__ avs, const float* __restrict__ avd, __half* __restrict__ Hout,
    float* __restrict__ as_out, float* __restrict__ ad_out, int n) {
    extern __shared__ __align__(16) char sm[];
    constexpr int NOUT = 64;
    constexpr int NT = 8;
    constexpr int WST = 576;
    const uint32_t OFF_AVS = 0;
    const uint32_t OFF_AVD = 256;
    const uint32_t OFF_W = 512;

    const int tid = threadIdx.x;
    const int row0 = blockIdx.x * 128;

    if (tid < NOUT) {
        reinterpret_cast<float*>(sm + OFF_AVS)[tid] = avs[tid];
        reinterpret_cast<float*>(sm + OFF_AVD)[tid] = avd[tid];
    }
    {
        const uint4* wsrc = reinterpret_cast<const uint4*>(Wpk);
#pragma unroll
        for (int i = tid; i < NOUT * 32; i += 256) {
            int nr = i >> 5;
            int w = i & 31;
            *reinterpret_cast<uint4*>(sm + OFF_W + nr * WST + w * 16) = wsrc[i];
        }
    }
    __syncthreads();

    const int warp = tid >> 5;
    const int lane = tid & 31;
    const int g = lane >> 2;
    const int j = lane & 3;
    const int wm0 = warp * 16;

    const int rowA0 = row0 + wm0 + g;
    const int rowA1 = rowA0 + 8;
    const bool v0r = rowA0 < n;
    const bool v1r = rowA1 < n;
    const __half* a0p = A + (size_t)rowA0 * 128 + j * 2;
    const __half* a1p = A + (size_t)rowA1 * 128 + j * 2;

    float acc[NT][4];
#pragma unroll
    for (int nt = 0; nt < NT; nt++)
#pragma unroll
        for (int q = 0; q < 4; q++) acc[nt][q] = 0.f;

    const char* bw = sm + OFF_W + g * WST + j * 16;
#pragma unroll
    for (int ks = 0; ks < 8; ks++) {
        uint32_t a[4];
        a[0] = v0r ? *reinterpret_cast<const uint32_t*>(a0p + ks * 16) : 0u;
        a[1] = v1r ? *reinterpret_cast<const uint32_t*>(a1p + ks * 16) : 0u;
        a[2] = v0r ? *reinterpret_cast<const uint32_t*>(a0p + ks * 16 + 8) : 0u;
        a[3] = v1r ? *reinterpret_cast<const uint32_t*>(a1p + ks * 16 + 8) : 0u;
        const char* bks = bw + ks * 64;
#pragma unroll
        for (int nt = 0; nt < NT; nt++) {
            uint4 b = *reinterpret_cast<const uint4*>(bks + nt * 8 * WST);
            mma_f16(acc[nt], a, b.x, b.y);
            mma_f16(acc[nt], a, b.z, b.w);
        }
    }

    const float* avs_s = reinterpret_cast<const float*>(sm + OFF_AVS);
    const float* avd_s = reinterpret_cast<const float*>(sm + OFF_AVD);
    float asum[2] = {0.f, 0.f};
    float dsum[2] = {0.f, 0.f};
#pragma unroll
    for (int nt = 0; nt < NT; nt++) {
        int cn = nt * 8 + 2 * j;
        float av0 = avs_s[cn];
        float av1 = avs_s[cn + 1];
        float dv0 = avd_s[cn];
        float dv1 = avd_s[cn + 1];
        asum[0] += acc[nt][0] * av0 + acc[nt][1] * av1;
        asum[1] += acc[nt][2] * av0 + acc[nt][3] * av1;
        dsum[0] += acc[nt][0] * dv0 + acc[nt][1] * dv1;
        dsum[1] += acc[nt][2] * dv0 + acc[nt][3] * dv1;
        if (v0r)
            *reinterpret_cast<__half2*>(Hout + (size_t)rowA0 * NOUT + cn) =
                __floats2half2_rn(acc[nt][0], acc[nt][1]);
        if (v1r)
            *reinterpret_cast<__half2*>(Hout + (size_t)rowA1 * NOUT + cn) =
                __floats2half2_rn(acc[nt][2], acc[nt][3]);
    }
#pragma unroll
    for (int off = 1; off <= 2; off <<= 1) {
        asum[0] += __shfl_xor_sync(0xffffffffu, asum[0], off);
        asum[1] += __shfl_xor_sync(0xffffffffu, asum[1], off);
        dsum[0] += __shfl_xor_sync(0xffffffffu, dsum[0], off);
        dsum[1] += __shfl_xor_sync(0xffffffffu, dsum[1], off);
    }
    if (j == 0) {
        if (v0r) {
            as_out[rowA0] = asum[0];
            ad_out[rowA0] = dsum[0];
        }
        if (v1r) {
            as_out[rowA1] = asum[1];
            ad_out[rowA1] = dsum[1];
        }
    }
}

// ---------------- CSR build ----------------
__global__ void deg_count(const int* __restrict__ ei, int* __restrict__ deg, int E) {
    int i = blockIdx.x * blockDim.x + threadIdx.x;
    if (i < E) atomicAdd(&deg[ei[E + i]], 1);
}

__global__ void scan_block(const int* __restrict__ deg, int* __restrict__ incl,
                           int* __restrict__ bsum, int n) {
    __shared__ int wsum[32];
    int tid = threadIdx.x;
    int lane = tid & 31;
    int wid = tid >> 5;
    int gid = blockIdx.x * 1024 + tid;
    int v = (gid < n) ? deg[gid] : 0;
#pragma unroll
    for (int off = 1; off < 32; off <<= 1) {
        int t = __shfl_up_sync(0xffffffffu, v, off);
        if (lane >= off) v += t;
    }
    if (lane == 31) wsum[wid] = v;
    __syncthreads();
    if (wid == 0) {
        int w = wsum[lane];
#pragma unroll
        for (int off = 1; off < 32; off <<= 1) {
            int t = __shfl_up_sync(0xffffffffu, w, off);
            if (lane >= off) w += t;
        }
        wsum[lane] = w;
    }
    __syncthreads();
    if (wid > 0) v += wsum[wid - 1];
    if (gid < n) incl[gid] = v;
    if (tid == 1023) bsum[blockIdx.x] = v;
}

__global__ void scan_finish(const int* __restrict__ incl, const int* __restrict__ bsum,
                            const int* __restrict__ deg, int* __restrict__ rowptr,
                            int* __restrict__ cursor, int n, int nb) {
    __shared__ int pre[128];
    int tid = threadIdx.x;
    if (tid < 32) {
        int base = tid * 4;
        int v[4];
#pragma unroll
        for (int q = 0; q < 4; q++) v[q] = (base + q < nb) ? bsum[base + q] : 0;
        int tot = v[0] + v[1] + v[2] + v[3];
        int inc = tot;
#pragma unroll
        for (int off = 1; off < 32; off <<= 1) {
            int t = __shfl_up_sync(0xffffffffu, inc, off);
            if (tid >= off) inc += t;
        }
        int run = inc - tot;
#pragma unroll
        for (int q = 0; q < 4; q++) {
            pre[base + q] = run;
            run += v[q];
        }
    }
    __syncthreads();
    int i = blockIdx.x * blockDim.x + tid;
    if (i < n) {
        int end = incl[i] + pre[i >> 10];
        rowptr[i + 1] = end;
        cursor[i] = end - deg[i];
    }
    if (i == 0) rowptr[0] = 0;
}

__global__ void scatter_edges(const int* __restrict__ ei, int* __restrict__ cursor,
                              int* __restrict__ adj, int E, int n) {
    int i = blockIdx.x * blockDim.x + threadIdx.x;
    if (i >= E + n) return;
    int s;
    int d;
    if (i < E) {
        s = ei[i];
        d = ei[E + i];
    } else {
        s = i - E;
        d = s;
    }
    int pos = atomicAdd(&cursor[d], 1);
    adj[pos] = s;
}

// ---------------- layer1 node aggregation (fp16 gather, fp16 out) ----------------
__global__ void gat_node1(const int* __restrict__ rowptr, const int* __restrict__ adj,
                          const float* __restrict__ as, const float* __restrict__ ad,
                          const __half* __restrict__ h, const float* __restrict__ b,
                          __half* __restrict__ out, int n) {
    int node = (blockIdx.x * blockDim.x + threadIdx.x) >> 5;
    int lane = threadIdx.x & 31;
    if (node >= n) return;
    int start = rowptr[node];
    int end = rowptr[node + 1];
    float ad0 = ad[node * 2];
    float ad1 = ad[node * 2 + 1];
    bool hi = lane >= 16;

    float4 acc = make_float4(0.f, 0.f, 0.f, 0.f);
    float den0 = 0.f;
    float den1 = 0.f;
    for (int base = start; base < end; base += 32) {
        int cnt = min(32, end - base);
        int s_l = 0;
        float ex0_l = 0.f;
        float ex1_l = 0.f;
        if (lane < cnt) {
            s_l = adj[base + lane];
            float e0 = as[s_l * 2] + ad0;
            e0 = e0 >= 0.f ? e0 : 0.2f * e0;
            float e1 = as[s_l * 2 + 1] + ad1;
            e1 = e1 >= 0.f ? e1 : 0.2f * e1;
            ex0_l = expf(e0);
            ex1_l = expf(e1);
        }
        den0 += ex0_l;
        den1 += ex1_l;
#pragma unroll 4
        for (int tt = 0; tt < cnt; tt++) {
            int s = __shfl_sync(0xffffffffu, s_l, tt);
            float ex0 = __shfl_sync(0xffffffffu, ex0_l, tt);
            float ex1 = __shfl_sync(0xffffffffu, ex1_l, tt);
            float ex = hi ? ex1 : ex0;
            uint2 u = reinterpret_cast<const uint2*>(h + (size_t)s * 128)[lane];
            __half2 p0 = *reinterpret_cast<const __half2*>(&u.x);
            __half2 p1 = *reinterpret_cast<const __half2*>(&u.y);
            float2 f0 = __half22float2(p0);
            float2 f1 = __half22float2(p1);
            acc.x = fmaf(ex, f0.x, acc.x);
            acc.y = fmaf(ex, f0.y, acc.y);
            acc.z = fmaf(ex, f1.x, acc.z);
            acc.w = fmaf(ex, f1.y, acc.w);
        }
    }
    for (int o = 16; o > 0; o >>= 1) {
        den0 += __shfl_xor_sync(0xffffffffu, den0, o);
        den1 += __shfl_xor_sync(0xffffffffu, den1, o);
    }
    float den = fmaxf(hi ? den1 : den0, 1e-16f);
    float inv = 1.f / den;
    float4 bb = reinterpret_cast<const float4*>(b)[lane];
    __half2 o0 = __floats2half2_rn(fmaxf(fmaf(acc.x, inv, bb.x), 0.f),
                                   fmaxf(fmaf(acc.y, inv, bb.y), 0.f));
    __half2 o1v = __floats2half2_rn(fmaxf(fmaf(acc.z, inv, bb.z), 0.f),
                                    fmaxf(fmaf(acc.w, inv, bb.w), 0.f));
    uint2 u;
    u.x = *reinterpret_cast<uint32_t*>(&o0);
    u.y = *reinterpret_cast<uint32_t*>(&o1v);
    reinterpret_cast<uint2*>(out + (size_t)node * 128)[lane] = u;
}

// ---------------- layer2 node aggregation (fp16 gather) ----------------
__global__ void gat_node2(const int* __restrict__ rowptr, const int* __restrict__ adj,
                          const float* __restrict__ as, const float* __restrict__ ad,
                          const __half* __restrict__ h, const float* __restrict__ b,
                          float* __restrict__ out, int n) {
    int node = (blockIdx.x * blockDim.x + threadIdx.x) >> 5;
    int lane = threadIdx.x & 31;
    if (node >= n) return;
    int start = rowptr[node];
    int end = rowptr[node + 1];
    float add = ad[node];

    float2 acc = make_float2(0.f, 0.f);
    float den = 0.f;
    for (int base = start; base < end; base += 32) {
        int cnt = min(32, end - base);
        int s_l = 0;
        float ex_l = 0.f;
        if (lane < cnt) {
            s_l = adj[base + lane];
            float e = as[s_l] + add;
            e = e >= 0.f ? e : 0.2f * e;
            ex_l = expf(e);
        }
        den += ex_l;
#pragma unroll 4
        for (int tt = 0; tt < cnt; tt++) {
            int s = __shfl_sync(0xffffffffu, s_l, tt);
            float ex = __shfl_sync(0xffffffffu, ex_l, tt);
            __half2 p = reinterpret_cast<const __half2*>(h + (size_t)s * 64)[lane];
            float2 f = __half22float2(p);
            acc.x = fmaf(ex, f.x, acc.x);
            acc.y = fmaf(ex, f.y, acc.y);
        }
    }
    for (int o = 16; o > 0; o >>= 1) {
        den += __shfl_xor_sync(0xffffffffu, den, o);
    }
    float inv = 1.f / fmaxf(den, 1e-16f);
    float2 bb = reinterpret_cast<const float2*>(b)[lane];
    float2 o;
    o.x = fmaf(acc.x, inv, bb.x);
    o.y = fmaf(acc.y, inv, bb.y);
    reinterpret_cast<float2*>(out + (size_t)node * 64)[lane] = o;
}

// ---------------- per-graph pooling (batch sorted) ----------------
__global__ void pool_seg(const float* __restrict__ h, const int* __restrict__ batch,
                         float* __restrict__ psum, float* __restrict__ pmax,
                         float* __restrict__ cnt, int n) {
    int n0 = blockIdx.x * 128;
    int t = threadIdx.x;
    int c = t & 63;
    int off = t >> 6;
    int gcur = -1;
    float sum = 0.f;
    float mx = -FLT_MAX;
    float count = 0.f;
    int lim = min(n0 + 128, n);
    for (int i = n0 + off; i < lim; i += 4) {
        int g = batch[i];
        if (g != gcur) {
            if (gcur >= 0) {
                atomicAdd(&psum[gcur * 64 + c], sum);
                atomicMaxF(&pmax[gcur * 64 + c], mx);
                if (c == 0) atomicAdd(&cnt[gcur], count);
            }
            gcur = g;
            sum = 0.f;
            mx = -FLT_MAX;
            count = 0.f;
        }
        float v = h[(size_t)i * 64 + c];
        sum += v;
        mx = fmaxf(mx, v);
        count += 1.f;
    }
    if (gcur >= 0) {
        atomicAdd(&psum[gcur * 64 + c], sum);
        atomicMaxF(&pmax[gcur * 64 + c], mx);
        if (c == 0) atomicAdd(&cnt[gcur], count);
    }
}

// ---------------- final MLP head ----------------
__global__ void final_mlp_kernel(const float* __restrict__ psum, const float* __restrict__ pmax,
                                 const float* __restrict__ cnt, const float* __restrict__ Wf1,
                                 const float* __restrict__ bf1, const float* __restrict__ Wf2,
                                 const float* __restrict__ bf2, float* __restrict__ out) {
    __shared__ float pooled[128];
    __shared__ float red[64];
    int g = blockIdx.x;
    int t = threadIdx.x;
    float c = cnt[g];
    pooled[t] = psum[g * 64 + t] / fmaxf(c, 1.f);
    pooled[64 + t] = (c > 0.f) ? pmax[g * 64 + t] : 0.f;
    __syncthreads();
    float hj = bf1[t];
    for (int k = 0; k < 128; k++) {
        hj = fmaf(pooled[k], Wf1[k * 64 + t], hj);
    }
    hj = fmaxf(hj, 0.f);
    red[t] = hj * Wf2[t];
    __syncthreads();
    for (int s = 32; s > 0; s >>= 1) {
        if (t < s) red[t] += red[t + s];
        __syncthreads();
    }
    if (t == 0) out[g] = red[0] + bf2[0];
}

// ---------------- host launch ----------------
static inline int cdiv(int a, int b) { return (a + b - 1) / b; }

extern "C" void kernel_launch(void* const* d_in, const int* in_sizes, int n_in,
                              void* d_out, int out_size) {
    const float* x = (const float*)d_in[0];
    const int* ei = (const int*)d_in[1];
    const int* bat = (const int*)d_in[2];
    const float* W1 = (const float*)d_in[3];
    const float* as1 = (const float*)d_in[4];
    const float* ad1 = (const float*)d_in[5];
    const float* b1 = (const float*)d_in[6];
    const float* W2 = (const float*)d_in[7];
    const float* as2 = (const float*)d_in[8];
    const float* ad2 = (const float*)d_in[9];
    const float* b2 = (const float*)d_in[10];
    const float* Wf1 = (const float*)d_in[11];
    const float* bf1 = (const float*)d_in[12];
    const float* Wf2 = (const float*)d_in[13];
    const float* bf2 = (const float*)d_in[14];
    float* out = (float*)d_out;

    const int n = in_sizes[0] / 128;
    const int E = in_sizes[1] / 2;
    const int G = out_size;

    __half* p_h1;
    __half* p_o1;
    __half* p_h2;
    float* p_o2;
    float* p_as1;
    float* p_ad1;
    float* p_as2;
    float* p_ad2;
    float* p_psum;
    float* p_pmax;
    float* p_cnt;
    int* p_deg;
    int* p_incl;
    int* p_bsum;
    int* p_rowptr;
    int* p_cursor;
    int* p_adj;
    uint32_t* p_w1pk;
    uint32_t* p_w2pk;
    cudaGetSymbolAddress((void**)&p_h1, g_h1);
    cudaGetSymbolAddress((void**)&p_o1, g_o1);
    cudaGetSymbolAddress((void**)&p_h2, g_h2);
    cudaGetSymbolAddress((void**)&p_o2, g_o2);
    cudaGetSymbolAddress((void**)&p_as1, g_as1);
    cudaGetSymbolAddress((void**)&p_ad1, g_ad1);
    cudaGetSymbolAddress((void**)&p_as2, g_as2);
    cudaGetSymbolAddress((void**)&p_ad2, g_ad2);
    cudaGetSymbolAddress((void**)&p_psum, g_psum);
    cudaGetSymbolAddress((void**)&p_pmax, g_pmax);
    cudaGetSymbolAddress((void**)&p_cnt, g_cnt);
    cudaGetSymbolAddress((void**)&p_deg, g_deg);
    cudaGetSymbolAddress((void**)&p_incl, g_incl);
    cudaGetSymbolAddress((void**)&p_bsum, g_bsum);
    cudaGetSymbolAddress((void**)&p_rowptr, g_rowptr);
    cudaGetSymbolAddress((void**)&p_cursor, g_cursor);
    cudaGetSymbolAddress((void**)&p_adj, g_adj);
    cudaGetSymbolAddress((void**)&p_w1pk, g_w1pk);
    cudaGetSymbolAddress((void**)&p_w2pk, g_w2pk);

    const int TB = 256;
    const int nb = cdiv(n, 1024);

    const int SMEM1 = 1024 + 128 * 576;  // 74752
    const int SMEM2 = 512 + 64 * 576;    // 37376
    cudaFuncSetAttribute(gemm_mma1, cudaFuncAttributeMaxDynamicSharedMemorySize, SMEM1);
    cudaFuncSetAttribute(gemm_mma2, cudaFuncAttributeMaxDynamicSharedMemorySize, SMEM2);

    static cudaStream_t s2 = nullptr;
    static cudaEvent_t evA = nullptr;
    static cudaEvent_t evB = nullptr;
    if (s2 == nullptr) {
        cudaStreamCreateWithFlags(&s2, cudaStreamNonBlocking);
        cudaEventCreateWithFlags(&evA, cudaEventDisableTiming);
        cudaEventCreateWithFlags(&evB, cudaEventDisableTiming);
    }

    // launch 0: setup (packed weights + deg init + pool fills)
    setup_kernel<<<cdiv(n, TB), TB>>>(W1, W2, p_w1pk, p_w2pk, p_deg, p_psum, p_pmax, p_cnt, n, G);

    // fork CSR chain to side stream
    cudaEventRecord(evA, 0);
    cudaStreamWaitEvent(s2, evA, 0);
    deg_count<<<cdiv(E, TB), TB, 0, s2>>>(ei, p_deg, E);        // launch 1
    scan_block<<<nb, 1024, 0, s2>>>(p_deg, p_incl, p_bsum, n);  // launch 2

    // launch 3 (profiled slot): layer-1 GEMM on main stream
    gemm_mma1<<<cdiv(n, 128), 256, SMEM1>>>(x, p_w1pk, as1, ad1, p_h1, p_as1, p_ad1, n);

    scan_finish<<<cdiv(n, TB), TB, 0, s2>>>(p_incl, p_bsum, p_deg, p_rowptr, p_cursor, n, nb);
    scatter_edges<<<cdiv(E + n, TB), TB, 0, s2>>>(ei, p_cursor, p_adj, E, n);
    cudaEventRecord(evB, s2);

    // join: gat_node1 needs gemm1 + CSR
    cudaStreamWaitEvent(0, evB, 0);
    gat_node1<<<cdiv(n * 32, TB), TB>>>(p_rowptr, p_adj, p_as1, p_ad1, p_h1, b1, p_o1, n);

    // layer 2
    gemm_mma2<<<cdiv(n, 128), 256, SMEM2>>>(p_o1, p_w2pk, as2, ad2, p_h2, p_as2, p_ad2, n);
    gat_node2<<<cdiv(n * 32, TB), TB>>>(p_rowptr, p_adj, p_as2, p_ad2, p_h2, b2, p_o2, n);

    // pooling + head
    pool_seg<<<cdiv(n, 128), 256>>>(p_o2, bat, p_psum, p_pmax, p_cnt, n);
    final_mlp_kernel<<<G, 64>>>(p_psum, p_pmax, p_cnt, Wf1, bf1, Wf2, bf2, out);
}